// round 3
// baseline (speedup 1.0000x reference)
#include <cuda_runtime.h>

#define SEQ 4096
#define DMODEL 1024
#define NHEADS 16
#define HDIM 64
#define QKV_N 3072

// Scratch (static device arrays — no allocation)
__device__ float g_qkv[SEQ * QKV_N];   // [S, 3D]: q | k | v
__device__ float g_ctx[SEQ * DMODEL];  // [S, D]

// ---------------------------------------------------------------------------
// tf32 helpers
// ---------------------------------------------------------------------------
__device__ __forceinline__ unsigned f2tf(float f) {
    unsigned u;
    asm("cvt.rna.tf32.f32 %0, %1;" : "=r"(u) : "f"(f));
    return u;
}

__device__ __forceinline__ void mma_tf32(float c[4], const unsigned a[4], const unsigned b[2]) {
    asm volatile(
        "mma.sync.aligned.m16n8k8.row.col.f32.tf32.tf32.f32 "
        "{%0,%1,%2,%3},{%4,%5,%6,%7},{%8,%9},{%0,%1,%2,%3};"
        : "+f"(c[0]), "+f"(c[1]), "+f"(c[2]), "+f"(c[3])
        : "r"(a[0]), "r"(a[1]), "r"(a[2]), "r"(a[3]), "r"(b[0]), "r"(b[1]));
}

__device__ __forceinline__ void cp16(void* dst_smem, const void* src_gmem) {
    unsigned d = (unsigned)__cvta_generic_to_shared(dst_smem);
    asm volatile("cp.async.cg.shared.global [%0], [%1], 16;" :: "r"(d), "l"(src_gmem));
}
#define CP_COMMIT() asm volatile("cp.async.commit_group;")
#define CP_WAIT1()  asm volatile("cp.async.wait_group 1;")

// ---------------------------------------------------------------------------
// TF32 tensor-core GEMM, cp.async 3-stage pipeline.
// C[M,N] = A[M,K] @ B[K,N] + bias[N]
// BM=128, BN=128, BK=32. 256 threads = 8 warps (4m x 2n); warp tile 32x64.
// Raw fp32 staged in smem; cvt->tf32 at fragment-load time.
// ---------------------------------------------------------------------------
#define GAP 36    // A smem pitch (floats): (4g+tig) unique mod 32
#define GBP 136   // B smem pitch (floats): (8tig+g) unique mod 32
#define STAGES 3
#define A_STG (128 * GAP)
#define B_STG (32 * GBP)

__global__ __launch_bounds__(256) void gemm_tf32_kernel(
    const float* __restrict__ A, const float* __restrict__ B,
    const float* __restrict__ bias, float* __restrict__ C,
    int M, int N, int K) {
    extern __shared__ float smg[];
    float* As = smg;                      // [STAGES][128][GAP]
    float* Bs = smg + STAGES * A_STG;     // [STAGES][32][GBP]

    int tid = threadIdx.x;
    int wid = tid >> 5, lane = tid & 31;
    int g = lane >> 2, tig = lane & 3;
    int warp_m = wid >> 1, warp_n = wid & 1;
    int bm = blockIdx.y * 128, bn = blockIdx.x * 128;

    // per-thread load coordinates
    int ar  = tid >> 1;                // 0..127
    int ac4 = (tid & 1) * 16;          // 0 or 16 (two cp16 each, +0/+4... see below)
    int br  = tid >> 3;                // 0..31
    int bc4 = (tid & 7) * 16;          // 0..112

    auto load_tile = [&](int stg, int k0) {
        float* Ad = As + stg * A_STG;
        float* Bd = Bs + stg * B_STG;
        // A tile: 128 x 32 floats = 1024 x 16B; 4 per thread
        #pragma unroll
        for (int i = 0; i < 2; i++) {
            int c = ac4 + i * 8;   // covers ac4..ac4+12 with 2 cp16 per i? no:
            cp16(&Ad[ar * GAP + c],     &A[(size_t)(bm + ar) * K + k0 + c]);
            cp16(&Ad[ar * GAP + c + 4], &A[(size_t)(bm + ar) * K + k0 + c + 4]);
        }
        // B tile: 32 x 128 floats = 1024 x 16B; 4 per thread
        #pragma unroll
        for (int i = 0; i < 2; i++) {
            int c = bc4 + i * 8;
            cp16(&Bd[br * GBP + c],     &B[(size_t)(k0 + br) * N + bn + c]);
            cp16(&Bd[br * GBP + c + 4], &B[(size_t)(k0 + br) * N + bn + c + 4]);
        }
    };

    float acc[2][8][4];
    #pragma unroll
    for (int mc = 0; mc < 2; mc++)
        #pragma unroll
        for (int nc = 0; nc < 8; nc++)
            #pragma unroll
            for (int i = 0; i < 4; i++) acc[mc][nc][i] = 0.0f;

    int kt_total = K >> 5;   // K/32

    // prologue: stages 0..STAGES-2
    load_tile(0, 0);
    CP_COMMIT();
    load_tile(1, 32);
    CP_COMMIT();

    for (int kt = 0; kt < kt_total; kt++) {
        CP_WAIT1();          // oldest group (stage kt) complete
        __syncthreads();     // visible to all; also guards WAR on stage (kt+2)%3

        int kn = kt + STAGES - 1;
        if (kn < kt_total) load_tile(kn % STAGES, kn * 32);
        CP_COMMIT();         // empty group ok at tail

        const float* Ac = As + (kt % STAGES) * A_STG;
        const float* Bc = Bs + (kt % STAGES) * B_STG;

        #pragma unroll
        for (int kc = 0; kc < 4; kc++) {
            unsigned a[2][4];
            #pragma unroll
            for (int mc = 0; mc < 2; mc++) {
                int row = warp_m * 32 + mc * 16;
                a[mc][0] = f2tf(Ac[(row + g) * GAP + kc * 8 + tig]);
                a[mc][1] = f2tf(Ac[(row + g + 8) * GAP + kc * 8 + tig]);
                a[mc][2] = f2tf(Ac[(row + g) * GAP + kc * 8 + tig + 4]);
                a[mc][3] = f2tf(Ac[(row + g + 8) * GAP + kc * 8 + tig + 4]);
            }
            #pragma unroll
            for (int nc = 0; nc < 8; nc++) {
                unsigned b[2];
                int col = warp_n * 64 + nc * 8 + g;
                b[0] = f2tf(Bc[(kc * 8 + tig) * GBP + col]);
                b[1] = f2tf(Bc[(kc * 8 + tig + 4) * GBP + col]);
                mma_tf32(acc[0][nc], a[0], b);
                mma_tf32(acc[1][nc], a[1], b);
            }
        }
    }

    // Epilogue: bias + store (C-frag layout)
    #pragma unroll
    for (int nc = 0; nc < 8; nc++) {
        int col = bn + warp_n * 64 + nc * 8 + 2 * tig;
        float bv0 = bias[col], bv1 = bias[col + 1];
        #pragma unroll
        for (int mc = 0; mc < 2; mc++) {
            int row = bm + warp_m * 32 + mc * 16 + g;
            float2 o0 = make_float2(acc[mc][nc][0] + bv0, acc[mc][nc][1] + bv1);
            float2 o1 = make_float2(acc[mc][nc][2] + bv0, acc[mc][nc][3] + bv1);
            *(float2*)&C[(size_t)row * N + col]       = o0;
            *(float2*)&C[(size_t)(row + 8) * N + col] = o1;
        }
    }
}

// ---------------------------------------------------------------------------
// Flash attention (causal) with tf32 mma. One CTA per (q-block 128, head).
// 256 threads = 8 warps; warp w owns rows 16w..16w+15. K/V tiles of 64.
// ---------------------------------------------------------------------------
#define QP 68   // pitch: (4g+tig) unique mod 32
#define VP 72   // pitch: (8tig+g) unique mod 32
#define BMA 128 // q rows per CTA

__global__ __launch_bounds__(256) void attn_tf32_kernel() {
    extern __shared__ unsigned sm[];
    unsigned* Qs = sm;                  // [128][68]  row=q, col=hd
    unsigned* Ks = Qs + BMA * QP;       // [64][68]   row=kpos, col=hd
    unsigned* Ps = Ks + 64 * QP;        // [128][68]  row=q, col=kpos
    unsigned* Vs = Ps + BMA * QP;       // [64][72]   row=kpos, col=hd

    int qb = gridDim.x - 1 - blockIdx.x;  // longest CTAs first
    int h  = blockIdx.y;
    int tid = threadIdx.x;
    int wid = tid >> 5, lane = tid & 31;
    int g = lane >> 2, tig = lane & 3;
    int row0 = wid * 16;

    const int q_off = h * HDIM;
    const int k_off = DMODEL + h * HDIM;
    const int v_off = 2 * DMODEL + h * HDIM;

    // Load Q tile (128x64 = 2048 float4, 8 per thread), tf32-converted
    #pragma unroll
    for (int i = 0; i < 8; i++) {
        int linear = tid + i * 256;
        int r  = linear >> 4;
        int c4 = (linear & 15) * 4;
        float4 v = *(const float4*)&g_qkv[(size_t)(qb * BMA + r) * QKV_N + q_off + c4];
        Qs[r * QP + c4 + 0] = f2tf(v.x);
        Qs[r * QP + c4 + 1] = f2tf(v.y);
        Qs[r * QP + c4 + 2] = f2tf(v.z);
        Qs[r * QP + c4 + 3] = f2tf(v.w);
    }

    float o[8][4];
    #pragma unroll
    for (int nc = 0; nc < 8; nc++)
        #pragma unroll
        for (int i = 0; i < 4; i++) o[nc][i] = 0.0f;
    float m0 = -1e30f, m1 = -1e30f, l0 = 0.0f, l1 = 0.0f;

    int jb_max = 2 * qb + 1;   // inclusive

    for (int jb = 0; jb <= jb_max; jb++) {
        __syncthreads();  // prior reads of Ks/Vs complete
        // Load K and V tiles (64x64 each = 1024 float4, 4 per thread each)
        #pragma unroll
        for (int i = 0; i < 4; i++) {
            int linear = tid + i * 256;
            int r  = linear >> 4;
            int c4 = (linear & 15) * 4;
            size_t grow = (size_t)(jb * 64 + r) * QKV_N;
            float4 kv = *(const float4*)&g_qkv[grow + k_off + c4];
            Ks[r * QP + c4 + 0] = f2tf(kv.x);
            Ks[r * QP + c4 + 1] = f2tf(kv.y);
            Ks[r * QP + c4 + 2] = f2tf(kv.z);
            Ks[r * QP + c4 + 3] = f2tf(kv.w);
            float4 vv = *(const float4*)&g_qkv[grow + v_off + c4];
            Vs[r * VP + c4 + 0] = f2tf(vv.x);
            Vs[r * VP + c4 + 1] = f2tf(vv.y);
            Vs[r * VP + c4 + 2] = f2tf(vv.z);
            Vs[r * VP + c4 + 3] = f2tf(vv.w);
        }
        __syncthreads();

        // ---- S = Q @ K^T (16x64 per warp) ----
        float s[8][4];
        #pragma unroll
        for (int nc = 0; nc < 8; nc++)
            #pragma unroll
            for (int i = 0; i < 4; i++) s[nc][i] = 0.0f;

        #pragma unroll
        for (int kc = 0; kc < 8; kc++) {
            unsigned a[4];
            a[0] = Qs[(row0 + g) * QP + kc * 8 + tig];
            a[1] = Qs[(row0 + g + 8) * QP + kc * 8 + tig];
            a[2] = Qs[(row0 + g) * QP + kc * 8 + tig + 4];
            a[3] = Qs[(row0 + g + 8) * QP + kc * 8 + tig + 4];
            #pragma unroll
            for (int nc = 0; nc < 8; nc++) {
                unsigned b[2];
                b[0] = Ks[(nc * 8 + g) * QP + kc * 8 + tig];
                b[1] = Ks[(nc * 8 + g) * QP + kc * 8 + tig + 4];
                mma_tf32(s[nc], a, b);
            }
        }

        // scale + causal mask (last two jb blocks only)
        #pragma unroll
        for (int nc = 0; nc < 8; nc++)
            #pragma unroll
            for (int i = 0; i < 4; i++) s[nc][i] *= 0.125f;

        if (jb >= 2 * qb) {
            int coff = jb * 64 - qb * BMA;   // 0 or 64
            int r_lo = row0 + g, r_hi = row0 + g + 8;
            #pragma unroll
            for (int nc = 0; nc < 8; nc++) {
                int c0 = nc * 8 + 2 * tig + coff, c1 = c0 + 1;
                if (c0 > r_lo) s[nc][0] = -1e30f;
                if (c1 > r_lo) s[nc][1] = -1e30f;
                if (c0 > r_hi) s[nc][2] = -1e30f;
                if (c1 > r_hi) s[nc][3] = -1e30f;
            }
        }

        // row max (local, then across the 4-lane quad)
        float mx0 = -1e30f, mx1 = -1e30f;
        #pragma unroll
        for (int nc = 0; nc < 8; nc++) {
            mx0 = fmaxf(mx0, fmaxf(s[nc][0], s[nc][1]));
            mx1 = fmaxf(mx1, fmaxf(s[nc][2], s[nc][3]));
        }
        mx0 = fmaxf(mx0, __shfl_xor_sync(0xffffffffu, mx0, 1));
        mx0 = fmaxf(mx0, __shfl_xor_sync(0xffffffffu, mx0, 2));
        mx1 = fmaxf(mx1, __shfl_xor_sync(0xffffffffu, mx1, 1));
        mx1 = fmaxf(mx1, __shfl_xor_sync(0xffffffffu, mx1, 2));

        float mn0 = fmaxf(m0, mx0), mn1 = fmaxf(m1, mx1);
        float al0 = __expf(m0 - mn0), al1 = __expf(m1 - mn1);

        float rs0 = 0.0f, rs1 = 0.0f;
        #pragma unroll
        for (int nc = 0; nc < 8; nc++) {
            float p0 = __expf(s[nc][0] - mn0);
            float p1 = __expf(s[nc][1] - mn0);
            float p2 = __expf(s[nc][2] - mn1);
            float p3 = __expf(s[nc][3] - mn1);
            rs0 += p0 + p1;
            rs1 += p2 + p3;
            uint2 lo = make_uint2(f2tf(p0), f2tf(p1));
            uint2 hi = make_uint2(f2tf(p2), f2tf(p3));
            *(uint2*)&Ps[(row0 + g) * QP + nc * 8 + 2 * tig]     = lo;
            *(uint2*)&Ps[(row0 + g + 8) * QP + nc * 8 + 2 * tig] = hi;
        }
        rs0 += __shfl_xor_sync(0xffffffffu, rs0, 1);
        rs0 += __shfl_xor_sync(0xffffffffu, rs0, 2);
        rs1 += __shfl_xor_sync(0xffffffffu, rs1, 1);
        rs1 += __shfl_xor_sync(0xffffffffu, rs1, 2);

        l0 = l0 * al0 + rs0;
        l1 = l1 * al1 + rs1;
        m0 = mn0;
        m1 = mn1;
        #pragma unroll
        for (int nc = 0; nc < 8; nc++) {
            o[nc][0] *= al0; o[nc][1] *= al0;
            o[nc][2] *= al1; o[nc][3] *= al1;
        }
        __syncwarp();  // Ps rows are warp-private

        // ---- O += P @ V ----
        #pragma unroll
        for (int kc = 0; kc < 8; kc++) {
            unsigned a[4];
            a[0] = Ps[(row0 + g) * QP + kc * 8 + tig];
            a[1] = Ps[(row0 + g + 8) * QP + kc * 8 + tig];
            a[2] = Ps[(row0 + g) * QP + kc * 8 + tig + 4];
            a[3] = Ps[(row0 + g + 8) * QP + kc * 8 + tig + 4];
            #pragma unroll
            for (int nc = 0; nc < 8; nc++) {
                unsigned b[2];
                b[0] = Vs[(kc * 8 + tig) * VP + nc * 8 + g];
                b[1] = Vs[(kc * 8 + tig + 4) * VP + nc * 8 + g];
                mma_tf32(o[nc], a, b);
            }
        }
    }

    // Normalize and write ctx
    float inv0 = 1.0f / l0, inv1 = 1.0f / l1;
    #pragma unroll
    for (int nc = 0; nc < 8; nc++) {
        int col = h * HDIM + nc * 8 + 2 * tig;
        int r_lo = qb * BMA + row0 + g;
        float2 lo = make_float2(o[nc][0] * inv0, o[nc][1] * inv0);
        float2 hi = make_float2(o[nc][2] * inv1, o[nc][3] * inv1);
        *(float2*)&g_ctx[(size_t)r_lo * DMODEL + col]       = lo;
        *(float2*)&g_ctx[(size_t)(r_lo + 8) * DMODEL + col] = hi;
    }
}

// ---------------------------------------------------------------------------
extern "C" void kernel_launch(void* const* d_in, const int* in_sizes, int n_in,
                              void* d_out, int out_size) {
    (void)in_sizes; (void)n_in; (void)out_size;
    const float* x     = (const float*)d_in[0];
    const float* w_qkv = (const float*)d_in[1];
    const float* b_qkv = (const float*)d_in[2];
    const float* w_out = (const float*)d_in[3];
    const float* b_out = (const float*)d_in[4];
    float* out = (float*)d_out;

    float* qkv_ptr = nullptr;
    float* ctx_ptr = nullptr;
    cudaGetSymbolAddress((void**)&qkv_ptr, g_qkv);
    cudaGetSymbolAddress((void**)&ctx_ptr, g_ctx);

    const int GEMM_SMEM = STAGES * (A_STG + B_STG) * (int)sizeof(float);      // 107520
    const int ATTN_SMEM = (2 * BMA * QP + 64 * QP + 64 * VP) * (int)sizeof(unsigned); // 105472
    static bool attr_set = false;
    if (!attr_set) {
        cudaFuncSetAttribute(gemm_tf32_kernel,
                             cudaFuncAttributeMaxDynamicSharedMemorySize, GEMM_SMEM);
        cudaFuncSetAttribute(attn_tf32_kernel,
                             cudaFuncAttributeMaxDynamicSharedMemorySize, ATTN_SMEM);
        attr_set = true;
    }

    // 1) QKV projection
    gemm_tf32_kernel<<<dim3(QKV_N / 128, SEQ / 128), 256, GEMM_SMEM>>>(
        x, w_qkv, b_qkv, qkv_ptr, SEQ, QKV_N, DMODEL);

    // 2) Causal attention
    attn_tf32_kernel<<<dim3(SEQ / BMA, NHEADS), 256, ATTN_SMEM>>>();

    // 3) Output projection
    gemm_tf32_kernel<<<dim3(DMODEL / 128, SEQ / 128), 256, GEMM_SMEM>>>(
        ctx_ptr, w_out, b_out, out, SEQ, DMODEL, DMODEL);
}

// round 4
// speedup vs baseline: 1.0605x; 1.0605x over previous
#include <cuda_runtime.h>

#define SEQ 4096
#define DMODEL 1024
#define NHEADS 16
#define HDIM 64
#define QKV_N 3072

// Scratch (static device arrays — no allocation)
__device__ float g_qkv[SEQ * QKV_N];    // [S, 3D]: q | k | v (tf32-rounded bits)
__device__ float g_ctx[SEQ * DMODEL];   // [S, D]   (tf32-rounded bits)
__device__ float g_x_tf[SEQ * DMODEL];          // pre-rounded x
__device__ float g_wqkv_tf[DMODEL * QKV_N];     // pre-rounded w_qkv
__device__ float g_wout_tf[DMODEL * DMODEL];    // pre-rounded w_out

// ---------------------------------------------------------------------------
// helpers
// ---------------------------------------------------------------------------
__device__ __forceinline__ unsigned f2tf(float f) {
    unsigned u;
    asm("cvt.rna.tf32.f32 %0, %1;" : "=r"(u) : "f"(f));
    return u;
}

__device__ __forceinline__ void mma_tf32(float c[4], const unsigned a[4], const unsigned b[2]) {
    asm volatile(
        "mma.sync.aligned.m16n8k8.row.col.f32.tf32.tf32.f32 "
        "{%0,%1,%2,%3},{%4,%5,%6,%7},{%8,%9},{%0,%1,%2,%3};"
        : "+f"(c[0]), "+f"(c[1]), "+f"(c[2]), "+f"(c[3])
        : "r"(a[0]), "r"(a[1]), "r"(a[2]), "r"(a[3]), "r"(b[0]), "r"(b[1]));
}

__device__ __forceinline__ void cp16(void* dst_smem, const void* src_gmem) {
    unsigned d = (unsigned)__cvta_generic_to_shared(dst_smem);
    asm volatile("cp.async.cg.shared.global [%0], [%1], 16;" :: "r"(d), "l"(src_gmem));
}
#define CP_COMMIT() asm volatile("cp.async.commit_group;")
#define CP_WAIT0()  asm volatile("cp.async.wait_group 0;")
#define CP_WAIT1()  asm volatile("cp.async.wait_group 1;")

// Pre-round fp32 -> tf32 bit pattern (elementwise, float4)
__global__ void round_tf32_kernel(const float* __restrict__ in,
                                  float* __restrict__ out, int n4) {
    int i = blockIdx.x * blockDim.x + threadIdx.x;
    if (i >= n4) return;
    float4 v = ((const float4*)in)[i];
    uint4 u;
    u.x = f2tf(v.x); u.y = f2tf(v.y); u.z = f2tf(v.z); u.w = f2tf(v.w);
    ((uint4*)out)[i] = u;
}

// ---------------------------------------------------------------------------
// TF32 GEMM, 3-stage cp.async pipeline, tf32 bits in smem (no in-loop cvt).
// C[M,N] = A[M,K] @ B[K,N] + bias[N];  A,B pre-rounded to tf32 bits.
// BM=128, BN=128, BK=32. 256 threads = 8 warps (4m x 2n); warp tile 32x64.
// ---------------------------------------------------------------------------
#define GAP 36    // A smem pitch: (4g+tig) unique mod 32
#define GBP 136   // B smem pitch: (8tig+g) unique mod 32
#define STAGES 3
#define A_STG (128 * GAP)
#define B_STG (32 * GBP)

__global__ __launch_bounds__(256) void gemm_tf32_kernel(
    const float* __restrict__ A, const float* __restrict__ B,
    const float* __restrict__ bias, float* __restrict__ C,
    int M, int N, int K, int round_out) {
    extern __shared__ unsigned smg[];
    unsigned* As = smg;                      // [STAGES][128][GAP]
    unsigned* Bs = smg + STAGES * A_STG;     // [STAGES][32][GBP]

    int tid = threadIdx.x;
    int wid = tid >> 5, lane = tid & 31;
    int g = lane >> 2, tig = lane & 3;
    int warp_m = wid >> 1, warp_n = wid & 1;
    int bm = blockIdx.y * 128, bn = blockIdx.x * 128;

    int ar  = tid >> 1;                // 0..127
    int ac4 = (tid & 1) * 16;          // 0 or 16
    int br  = tid >> 3;                // 0..31
    int bc4 = (tid & 7) * 16;          // 0..112

    auto load_tile = [&](int stg, int k0) {
        unsigned* Ad = As + stg * A_STG;
        unsigned* Bd = Bs + stg * B_STG;
        #pragma unroll
        for (int i = 0; i < 2; i++) {
            int c = ac4 + i * 8;
            cp16(&Ad[ar * GAP + c],     &A[(size_t)(bm + ar) * K + k0 + c]);
            cp16(&Ad[ar * GAP + c + 4], &A[(size_t)(bm + ar) * K + k0 + c + 4]);
        }
        #pragma unroll
        for (int i = 0; i < 2; i++) {
            int c = bc4 + i * 8;
            cp16(&Bd[br * GBP + c],     &B[(size_t)(k0 + br) * N + bn + c]);
            cp16(&Bd[br * GBP + c + 4], &B[(size_t)(k0 + br) * N + bn + c + 4]);
        }
    };

    float acc[2][8][4];
    #pragma unroll
    for (int mc = 0; mc < 2; mc++)
        #pragma unroll
        for (int nc = 0; nc < 8; nc++)
            #pragma unroll
            for (int i = 0; i < 4; i++) acc[mc][nc][i] = 0.0f;

    int kt_total = K >> 5;

    load_tile(0, 0);
    CP_COMMIT();
    load_tile(1, 32);
    CP_COMMIT();

    for (int kt = 0; kt < kt_total; kt++) {
        CP_WAIT1();
        __syncthreads();

        int kn = kt + STAGES - 1;
        if (kn < kt_total) load_tile(kn % STAGES, kn * 32);
        CP_COMMIT();

        const unsigned* Ac = As + (kt % STAGES) * A_STG;
        const unsigned* Bc = Bs + (kt % STAGES) * B_STG;

        #pragma unroll
        for (int kc = 0; kc < 4; kc++) {
            unsigned a[2][4];
            #pragma unroll
            for (int mc = 0; mc < 2; mc++) {
                int row = warp_m * 32 + mc * 16;
                a[mc][0] = Ac[(row + g) * GAP + kc * 8 + tig];
                a[mc][1] = Ac[(row + g + 8) * GAP + kc * 8 + tig];
                a[mc][2] = Ac[(row + g) * GAP + kc * 8 + tig + 4];
                a[mc][3] = Ac[(row + g + 8) * GAP + kc * 8 + tig + 4];
            }
            #pragma unroll
            for (int nc = 0; nc < 8; nc++) {
                unsigned b[2];
                int col = warp_n * 64 + nc * 8 + g;
                b[0] = Bc[(kc * 8 + tig) * GBP + col];
                b[1] = Bc[(kc * 8 + tig + 4) * GBP + col];
                mma_tf32(acc[0][nc], a[0], b);
                mma_tf32(acc[1][nc], a[1], b);
            }
        }
    }

    // Epilogue: bias + (optional tf32 rounding) + store
    #pragma unroll
    for (int nc = 0; nc < 8; nc++) {
        int col = bn + warp_n * 64 + nc * 8 + 2 * tig;
        float bv0 = bias[col], bv1 = bias[col + 1];
        #pragma unroll
        for (int mc = 0; mc < 2; mc++) {
            int row = bm + warp_m * 32 + mc * 16 + g;
            float v00 = acc[mc][nc][0] + bv0, v01 = acc[mc][nc][1] + bv1;
            float v10 = acc[mc][nc][2] + bv0, v11 = acc[mc][nc][3] + bv1;
            if (round_out) {
                v00 = __uint_as_float(f2tf(v00)); v01 = __uint_as_float(f2tf(v01));
                v10 = __uint_as_float(f2tf(v10)); v11 = __uint_as_float(f2tf(v11));
            }
            *(float2*)&C[(size_t)row * N + col]       = make_float2(v00, v01);
            *(float2*)&C[(size_t)(row + 8) * N + col] = make_float2(v10, v11);
        }
    }
}

// ---------------------------------------------------------------------------
// Flash attention (causal), tf32 mma, cp.async double-buffered K/V.
// One CTA per (q-block 64, head). 128 threads = 4 warps.
// g_qkv already tf32-rounded -> no cvt on Q/K/V.
// ---------------------------------------------------------------------------
#define QP 68   // pitch: (4g+tig) unique mod 32
#define VP 72   // pitch: (8tig+g) unique mod 32

__global__ __launch_bounds__(128) void attn_tf32_kernel() {
    extern __shared__ unsigned sm[];
    unsigned* Qs = sm;                  // [64][68]
    unsigned* Ps = Qs + 64 * QP;        // [64][68]
    unsigned* Ks = Ps + 64 * QP;        // [2][64][68]
    unsigned* Vs = Ks + 2 * 64 * QP;    // [2][64][72]

    int qb = gridDim.x - 1 - blockIdx.x;  // longest CTAs first
    int h  = blockIdx.y;
    int tid = threadIdx.x;
    int wid = tid >> 5, lane = tid & 31;
    int g = lane >> 2, tig = lane & 3;
    int row0 = wid * 16;

    const int k_off = DMODEL + h * HDIM;
    const int v_off = 2 * DMODEL + h * HDIM;

    // cp.async loader for one K/V block into buffer `buf`
    auto cp_kv = [&](int jb, int buf) {
        unsigned* Kd = Ks + buf * 64 * QP;
        unsigned* Vd = Vs + buf * 64 * VP;
        #pragma unroll
        for (int i = 0; i < 8; i++) {
            int linear = tid + i * 128;
            int r  = linear >> 4;
            int c4 = (linear & 15) * 4;
            size_t grow = (size_t)(jb * 64 + r) * QKV_N;
            cp16(&Kd[r * QP + c4], &g_qkv[grow + k_off + c4]);
            cp16(&Vd[r * VP + c4], &g_qkv[grow + v_off + c4]);
        }
    };

    // kick off K/V block 0
    cp_kv(0, 0);
    CP_COMMIT();

    // Load Q tile (raw bits, already tf32)
    #pragma unroll
    for (int i = 0; i < 8; i++) {
        int linear = tid + i * 128;
        int r  = linear >> 4;
        int c4 = (linear & 15) * 4;
        float4 v = *(const float4*)&g_qkv[(size_t)(qb * 64 + r) * QKV_N + h * HDIM + c4];
        Qs[r * QP + c4 + 0] = __float_as_uint(v.x);
        Qs[r * QP + c4 + 1] = __float_as_uint(v.y);
        Qs[r * QP + c4 + 2] = __float_as_uint(v.z);
        Qs[r * QP + c4 + 3] = __float_as_uint(v.w);
    }

    float o[8][4];
    #pragma unroll
    for (int nc = 0; nc < 8; nc++)
        #pragma unroll
        for (int i = 0; i < 4; i++) o[nc][i] = 0.0f;
    float m0 = -1e30f, m1 = -1e30f, l0 = 0.0f, l1 = 0.0f;

    for (int jb = 0; jb <= qb; jb++) {
        int buf = jb & 1;
        CP_WAIT0();          // K/V block jb landed
        __syncthreads();     // visible to all; all reads of buf^1 (iter jb-1) done

        if (jb < qb) { cp_kv(jb + 1, buf ^ 1); CP_COMMIT(); }

        const unsigned* Kc = Ks + buf * 64 * QP;
        const unsigned* Vc = Vs + buf * 64 * VP;

        // ---- S = Q @ K^T (16x64 per warp) ----
        float s[8][4];
        #pragma unroll
        for (int nc = 0; nc < 8; nc++)
            #pragma unroll
            for (int i = 0; i < 4; i++) s[nc][i] = 0.0f;

        #pragma unroll
        for (int kc = 0; kc < 8; kc++) {
            unsigned a[4];
            a[0] = Qs[(row0 + g) * QP + kc * 8 + tig];
            a[1] = Qs[(row0 + g + 8) * QP + kc * 8 + tig];
            a[2] = Qs[(row0 + g) * QP + kc * 8 + tig + 4];
            a[3] = Qs[(row0 + g + 8) * QP + kc * 8 + tig + 4];
            #pragma unroll
            for (int nc = 0; nc < 8; nc++) {
                unsigned b[2];
                b[0] = Kc[(nc * 8 + g) * QP + kc * 8 + tig];
                b[1] = Kc[(nc * 8 + g) * QP + kc * 8 + tig + 4];
                mma_tf32(s[nc], a, b);
            }
        }

        #pragma unroll
        for (int nc = 0; nc < 8; nc++)
            #pragma unroll
            for (int i = 0; i < 4; i++) s[nc][i] *= 0.125f;

        if (jb == qb) {
            int r_lo = row0 + g, r_hi = row0 + g + 8;
            #pragma unroll
            for (int nc = 0; nc < 8; nc++) {
                int c0 = nc * 8 + 2 * tig, c1 = c0 + 1;
                if (c0 > r_lo) s[nc][0] = -1e30f;
                if (c1 > r_lo) s[nc][1] = -1e30f;
                if (c0 > r_hi) s[nc][2] = -1e30f;
                if (c1 > r_hi) s[nc][3] = -1e30f;
            }
        }

        float mx0 = -1e30f, mx1 = -1e30f;
        #pragma unroll
        for (int nc = 0; nc < 8; nc++) {
            mx0 = fmaxf(mx0, fmaxf(s[nc][0], s[nc][1]));
            mx1 = fmaxf(mx1, fmaxf(s[nc][2], s[nc][3]));
        }
        mx0 = fmaxf(mx0, __shfl_xor_sync(0xffffffffu, mx0, 1));
        mx0 = fmaxf(mx0, __shfl_xor_sync(0xffffffffu, mx0, 2));
        mx1 = fmaxf(mx1, __shfl_xor_sync(0xffffffffu, mx1, 1));
        mx1 = fmaxf(mx1, __shfl_xor_sync(0xffffffffu, mx1, 2));

        float mn0 = fmaxf(m0, mx0), mn1 = fmaxf(m1, mx1);
        float al0 = __expf(m0 - mn0), al1 = __expf(m1 - mn1);

        float rs0 = 0.0f, rs1 = 0.0f;
        #pragma unroll
        for (int nc = 0; nc < 8; nc++) {
            float p0 = __expf(s[nc][0] - mn0);
            float p1 = __expf(s[nc][1] - mn0);
            float p2 = __expf(s[nc][2] - mn1);
            float p3 = __expf(s[nc][3] - mn1);
            rs0 += p0 + p1;
            rs1 += p2 + p3;
            uint2 lo = make_uint2(f2tf(p0), f2tf(p1));
            uint2 hi = make_uint2(f2tf(p2), f2tf(p3));
            *(uint2*)&Ps[(row0 + g) * QP + nc * 8 + 2 * tig]     = lo;
            *(uint2*)&Ps[(row0 + g + 8) * QP + nc * 8 + 2 * tig] = hi;
        }
        rs0 += __shfl_xor_sync(0xffffffffu, rs0, 1);
        rs0 += __shfl_xor_sync(0xffffffffu, rs0, 2);
        rs1 += __shfl_xor_sync(0xffffffffu, rs1, 1);
        rs1 += __shfl_xor_sync(0xffffffffu, rs1, 2);

        l0 = l0 * al0 + rs0;
        l1 = l1 * al1 + rs1;
        m0 = mn0;
        m1 = mn1;
        #pragma unroll
        for (int nc = 0; nc < 8; nc++) {
            o[nc][0] *= al0; o[nc][1] *= al0;
            o[nc][2] *= al1; o[nc][3] *= al1;
        }
        __syncwarp();  // Ps rows are warp-private

        // ---- O += P @ V ----
        #pragma unroll
        for (int kc = 0; kc < 8; kc++) {
            unsigned a[4];
            a[0] = Ps[(row0 + g) * QP + kc * 8 + tig];
            a[1] = Ps[(row0 + g + 8) * QP + kc * 8 + tig];
            a[2] = Ps[(row0 + g) * QP + kc * 8 + tig + 4];
            a[3] = Ps[(row0 + g + 8) * QP + kc * 8 + tig + 4];
            #pragma unroll
            for (int nc = 0; nc < 8; nc++) {
                unsigned b[2];
                b[0] = Vc[(kc * 8 + tig) * VP + nc * 8 + g];
                b[1] = Vc[(kc * 8 + tig + 4) * VP + nc * 8 + g];
                mma_tf32(o[nc], a, b);
            }
        }
    }

    // Normalize, round to tf32 bits (feeds out-proj), write ctx
    float inv0 = 1.0f / l0, inv1 = 1.0f / l1;
    #pragma unroll
    for (int nc = 0; nc < 8; nc++) {
        int col = h * HDIM + nc * 8 + 2 * tig;
        int r_lo = qb * 64 + row0 + g;
        uint2 lo = make_uint2(f2tf(o[nc][0] * inv0), f2tf(o[nc][1] * inv0));
        uint2 hi = make_uint2(f2tf(o[nc][2] * inv1), f2tf(o[nc][3] * inv1));
        *(uint2*)&g_ctx[(size_t)r_lo * DMODEL + col]       = lo;
        *(uint2*)&g_ctx[(size_t)(r_lo + 8) * DMODEL + col] = hi;
    }
}

// ---------------------------------------------------------------------------
extern "C" void kernel_launch(void* const* d_in, const int* in_sizes, int n_in,
                              void* d_out, int out_size) {
    (void)in_sizes; (void)n_in; (void)out_size;
    const float* x     = (const float*)d_in[0];
    const float* w_qkv = (const float*)d_in[1];
    const float* b_qkv = (const float*)d_in[2];
    const float* w_out = (const float*)d_in[3];
    const float* b_out = (const float*)d_in[4];
    float* out = (float*)d_out;

    float *qkv_ptr, *ctx_ptr, *xtf_ptr, *wqkv_ptr, *wout_ptr;
    cudaGetSymbolAddress((void**)&qkv_ptr,  g_qkv);
    cudaGetSymbolAddress((void**)&ctx_ptr,  g_ctx);
    cudaGetSymbolAddress((void**)&xtf_ptr,  g_x_tf);
    cudaGetSymbolAddress((void**)&wqkv_ptr, g_wqkv_tf);
    cudaGetSymbolAddress((void**)&wout_ptr, g_wout_tf);

    const int GEMM_SMEM = STAGES * (A_STG + B_STG) * (int)sizeof(unsigned);            // 107520
    const int ATTN_SMEM = (2 * 64 * QP + 2 * 64 * QP + 2 * 64 * VP) * (int)sizeof(unsigned); // 106496
    static bool attr_set = false;
    if (!attr_set) {
        cudaFuncSetAttribute(gemm_tf32_kernel,
                             cudaFuncAttributeMaxDynamicSharedMemorySize, GEMM_SMEM);
        cudaFuncSetAttribute(attn_tf32_kernel,
                             cudaFuncAttributeMaxDynamicSharedMemorySize, ATTN_SMEM);
        attr_set = true;
    }

    // 0) Pre-round inputs to tf32 bit patterns
    round_tf32_kernel<<<(SEQ * DMODEL / 4 + 255) / 256, 256>>>(x, xtf_ptr, SEQ * DMODEL / 4);
    round_tf32_kernel<<<(DMODEL * QKV_N / 4 + 255) / 256, 256>>>(w_qkv, wqkv_ptr, DMODEL * QKV_N / 4);
    round_tf32_kernel<<<(DMODEL * DMODEL / 4 + 255) / 256, 256>>>(w_out, wout_ptr, DMODEL * DMODEL / 4);

    // 1) QKV projection (output tf32-rounded)
    gemm_tf32_kernel<<<dim3(QKV_N / 128, SEQ / 128), 256, GEMM_SMEM>>>(
        xtf_ptr, wqkv_ptr, b_qkv, qkv_ptr, SEQ, QKV_N, DMODEL, 1);

    // 2) Causal attention (output tf32-rounded)
    attn_tf32_kernel<<<dim3(SEQ / 64, NHEADS), 128, ATTN_SMEM>>>();

    // 3) Output projection (full fp32 output)
    gemm_tf32_kernel<<<dim3(DMODEL / 128, SEQ / 128), 256, GEMM_SMEM>>>(
        ctx_ptr, wout_ptr, b_out, out, SEQ, DMODEL, DMODEL, 0);
}

// round 6
// speedup vs baseline: 1.1416x; 1.0764x over previous
#include <cuda_runtime.h>

#define SEQ 4096
#define DMODEL 1024
#define NHEADS 16
#define HDIM 64
#define QKV_N 3072

// Scratch (static device arrays — no allocation)
__device__ float g_qkv[SEQ * QKV_N];    // [S, 3D]: q | k | v (tf32-rounded bits)
__device__ float g_ctx[SEQ * DMODEL];   // [S, D]   (tf32-rounded bits)
__device__ float g_x_tf[SEQ * DMODEL];          // pre-rounded x
__device__ float g_wqkv_tf[DMODEL * QKV_N];     // pre-rounded w_qkv
__device__ float g_wout_tf[DMODEL * DMODEL];    // pre-rounded w_out

// ---------------------------------------------------------------------------
// helpers
// ---------------------------------------------------------------------------
__device__ __forceinline__ unsigned f2tf(float f) {
    unsigned u;
    asm("cvt.rna.tf32.f32 %0, %1;" : "=r"(u) : "f"(f));
    return u;
}

__device__ __forceinline__ void mma_tf32(float c[4], const unsigned a[4], const unsigned b[2]) {
    asm volatile(
        "mma.sync.aligned.m16n8k8.row.col.f32.tf32.tf32.f32 "
        "{%0,%1,%2,%3},{%4,%5,%6,%7},{%8,%9},{%0,%1,%2,%3};"
        : "+f"(c[0]), "+f"(c[1]), "+f"(c[2]), "+f"(c[3])
        : "r"(a[0]), "r"(a[1]), "r"(a[2]), "r"(a[3]), "r"(b[0]), "r"(b[1]));
}

__device__ __forceinline__ void cp16(void* dst_smem, const void* src_gmem) {
    unsigned d = (unsigned)__cvta_generic_to_shared(dst_smem);
    asm volatile("cp.async.cg.shared.global [%0], [%1], 16;" :: "r"(d), "l"(src_gmem));
}
#define CP_COMMIT() asm volatile("cp.async.commit_group;")
#define CP_WAIT0()  asm volatile("cp.async.wait_group 0;")

// Pre-round fp32 -> tf32 bit pattern (elementwise, float4)
__global__ void round_tf32_kernel(const float* __restrict__ in,
                                  float* __restrict__ out, int n4) {
    int i = blockIdx.x * blockDim.x + threadIdx.x;
    if (i >= n4) return;
    float4 v = ((const float4*)in)[i];
    uint4 u;
    u.x = f2tf(v.x); u.y = f2tf(v.y); u.z = f2tf(v.z); u.w = f2tf(v.w);
    ((uint4*)out)[i] = u;
}

// ---------------------------------------------------------------------------
// TF32 GEMM: register double-buffered, 2-stage smem, one barrier per k-tile.
// C[M,N] = A[M,K] @ B[K,N] + bias[N];  A,B pre-rounded to tf32 bits.
// BM=128, BN=128, BK=16. 256 threads = 8 warps (4m x 2n); warp tile 32x64.
// Per k-tile each thread owns exactly 8 floats of A and 8 of B (2 x float4).
// ---------------------------------------------------------------------------
#define BKG 16
#define GAP 20     // A pitch: (20g+tig) mod 32 all distinct; 16B-aligned rows
#define GBP 136    // B pitch: (8tig+g) unique mod 32; 16B-aligned
#define A_STG (128 * GAP)           // 2560 words
#define B_STG (BKG * GBP)           // 2176 words
#define STG_TOT (A_STG + B_STG)     // 4736 words; x2 stages x4B = 37888 B

__global__ __launch_bounds__(256, 2) void gemm_tf32_kernel(
    const float* __restrict__ A, const float* __restrict__ B,
    const float* __restrict__ bias, float* __restrict__ C,
    int M, int N, int K, int round_out) {
    extern __shared__ float smg[];   // [2][STG_TOT]

    int tid = threadIdx.x;
    int wid = tid >> 5, lane = tid & 31;
    int g = lane >> 2, tig = lane & 3;
    int warp_m = wid >> 1, warp_n = wid & 1;
    int bm = blockIdx.y * 128, bn = blockIdx.x * 128;

    int ar = tid >> 1,  ac = (tid & 1) * 8;    // A: row 0..127, col 0/8
    int br = tid >> 4,  bc = (tid & 15) * 8;   // B: row 0..15,  col 0..120

    const float* Ag = A + (size_t)(bm + ar) * K + ac;
    const float* Bg = B + (size_t)br * N + bn + bc;

    float4 ra[2], rb[2];
    auto ldg = [&](int k0) {
        ra[0] = *(const float4*)(Ag + k0);
        ra[1] = *(const float4*)(Ag + k0 + 4);
        rb[0] = *(const float4*)(Bg + (size_t)k0 * N);
        rb[1] = *(const float4*)(Bg + (size_t)k0 * N + 4);
    };
    auto sts = [&](float* dst) {
        *(float4*)&dst[ar * GAP + ac]     = ra[0];
        *(float4*)&dst[ar * GAP + ac + 4] = ra[1];
        float* Bd = dst + A_STG;
        *(float4*)&Bd[br * GBP + bc]     = rb[0];
        *(float4*)&Bd[br * GBP + bc + 4] = rb[1];
    };

    float acc[2][8][4];
    #pragma unroll
    for (int mc = 0; mc < 2; mc++)
        #pragma unroll
        for (int nc = 0; nc < 8; nc++)
            #pragma unroll
            for (int i = 0; i < 4; i++) acc[mc][nc][i] = 0.0f;

    auto compute = [&](const float* buf) {
        const float* Ac = buf;
        const float* Bc = buf + A_STG;
        #pragma unroll
        for (int kc = 0; kc < 2; kc++) {
            unsigned a[2][4];
            #pragma unroll
            for (int mc = 0; mc < 2; mc++) {
                int row = warp_m * 32 + mc * 16;
                a[mc][0] = __float_as_uint(Ac[(row + g) * GAP + kc * 8 + tig]);
                a[mc][1] = __float_as_uint(Ac[(row + g + 8) * GAP + kc * 8 + tig]);
                a[mc][2] = __float_as_uint(Ac[(row + g) * GAP + kc * 8 + tig + 4]);
                a[mc][3] = __float_as_uint(Ac[(row + g + 8) * GAP + kc * 8 + tig + 4]);
            }
            #pragma unroll
            for (int nc = 0; nc < 8; nc++) {
                unsigned b[2];
                int col = warp_n * 64 + nc * 8 + g;
                b[0] = __float_as_uint(Bc[(kc * 8 + tig) * GBP + col]);
                b[1] = __float_as_uint(Bc[(kc * 8 + tig + 4) * GBP + col]);
                mma_tf32(acc[0][nc], a[0], b);
                mma_tf32(acc[1][nc], a[1], b);
            }
        }
    };

    int kt_total = K / BKG;   // 64

    // prologue: tile 0 into buffer 0
    ldg(0);
    sts(smg);
    __syncthreads();

    for (int kt = 0; kt < kt_total - 1; kt++) {
        ldg((kt + 1) * BKG);                // prefetch next tile into regs
        compute(smg + (kt & 1) * STG_TOT);  // compute current
        sts(smg + ((kt + 1) & 1) * STG_TOT);
        __syncthreads();
    }
    compute(smg + ((kt_total - 1) & 1) * STG_TOT);

    // Epilogue: bias + (optional tf32 rounding) + store
    #pragma unroll
    for (int nc = 0; nc < 8; nc++) {
        int col = bn + warp_n * 64 + nc * 8 + 2 * tig;
        float bv0 = bias[col], bv1 = bias[col + 1];
        #pragma unroll
        for (int mc = 0; mc < 2; mc++) {
            int row = bm + warp_m * 32 + mc * 16 + g;
            float v00 = acc[mc][nc][0] + bv0, v01 = acc[mc][nc][1] + bv1;
            float v10 = acc[mc][nc][2] + bv0, v11 = acc[mc][nc][3] + bv1;
            if (round_out) {
                v00 = __uint_as_float(f2tf(v00)); v01 = __uint_as_float(f2tf(v01));
                v10 = __uint_as_float(f2tf(v10)); v11 = __uint_as_float(f2tf(v11));
            }
            *(float2*)&C[(size_t)row * N + col]       = make_float2(v00, v01);
            *(float2*)&C[(size_t)(row + 8) * N + col] = make_float2(v10, v11);
        }
    }
}

// ---------------------------------------------------------------------------
// Flash attention (causal), tf32 mma, cp.async double-buffered K/V,
// Q fragments held in registers for the whole loop.
// One CTA per (q-block 64, head). 128 threads = 4 warps.
// ---------------------------------------------------------------------------
#define QP 68   // pitch: (4g+tig) unique mod 32
#define VP 72   // pitch: (8tig+g) unique mod 32

__global__ __launch_bounds__(128) void attn_tf32_kernel() {
    extern __shared__ unsigned sm[];
    unsigned* Ps = sm;                  // [64][68]
    unsigned* Ks = Ps + 64 * QP;        // [2][64][68]
    unsigned* Vs = Ks + 2 * 64 * QP;    // [2][64][72]

    int qb = gridDim.x - 1 - blockIdx.x;  // longest CTAs first
    int h  = blockIdx.y;
    int tid = threadIdx.x;
    int wid = tid >> 5, lane = tid & 31;
    int g = lane >> 2, tig = lane & 3;
    int row0 = wid * 16;

    const int k_off = DMODEL + h * HDIM;
    const int v_off = 2 * DMODEL + h * HDIM;

    auto cp_kv = [&](int jb, int buf) {
        unsigned* Kd = Ks + buf * 64 * QP;
        unsigned* Vd = Vs + buf * 64 * VP;
        #pragma unroll
        for (int i = 0; i < 8; i++) {
            int linear = tid + i * 128;
            int r  = linear >> 4;
            int c4 = (linear & 15) * 4;
            size_t grow = (size_t)(jb * 64 + r) * QKV_N;
            cp16(&Kd[r * QP + c4], &g_qkv[grow + k_off + c4]);
            cp16(&Vd[r * VP + c4], &g_qkv[grow + v_off + c4]);
        }
    };

    cp_kv(0, 0);
    CP_COMMIT();

    // Q fragments direct to registers (g_qkv already tf32 bits)
    unsigned qf[8][4];
    {
        const float* Qb = g_qkv + (size_t)(qb * 64) * QKV_N + h * HDIM;
        #pragma unroll
        for (int kc = 0; kc < 8; kc++) {
            qf[kc][0] = __float_as_uint(Qb[(size_t)(row0 + g) * QKV_N + kc * 8 + tig]);
            qf[kc][1] = __float_as_uint(Qb[(size_t)(row0 + g + 8) * QKV_N + kc * 8 + tig]);
            qf[kc][2] = __float_as_uint(Qb[(size_t)(row0 + g) * QKV_N + kc * 8 + tig + 4]);
            qf[kc][3] = __float_as_uint(Qb[(size_t)(row0 + g + 8) * QKV_N + kc * 8 + tig + 4]);
        }
    }

    float o[8][4];
    #pragma unroll
    for (int nc = 0; nc < 8; nc++)
        #pragma unroll
        for (int i = 0; i < 4; i++) o[nc][i] = 0.0f;
    float m0 = -1e30f, m1 = -1e30f, l0 = 0.0f, l1 = 0.0f;

    for (int jb = 0; jb <= qb; jb++) {
        int buf = jb & 1;
        CP_WAIT0();
        __syncthreads();

        if (jb < qb) { cp_kv(jb + 1, buf ^ 1); CP_COMMIT(); }

        const unsigned* Kc = Ks + buf * 64 * QP;
        const unsigned* Vc = Vs + buf * 64 * VP;

        // ---- S = Q @ K^T ----
        float s[8][4];
        #pragma unroll
        for (int nc = 0; nc < 8; nc++)
            #pragma unroll
            for (int i = 0; i < 4; i++) s[nc][i] = 0.0f;

        #pragma unroll
        for (int kc = 0; kc < 8; kc++) {
            #pragma unroll
            for (int nc = 0; nc < 8; nc++) {
                unsigned b[2];
                b[0] = Kc[(nc * 8 + g) * QP + kc * 8 + tig];
                b[1] = Kc[(nc * 8 + g) * QP + kc * 8 + tig + 4];
                mma_tf32(s[nc], qf[kc], b);
            }
        }

        #pragma unroll
        for (int nc = 0; nc < 8; nc++)
            #pragma unroll
            for (int i = 0; i < 4; i++) s[nc][i] *= 0.125f;

        if (jb == qb) {
            int r_lo = row0 + g, r_hi = row0 + g + 8;
            #pragma unroll
            for (int nc = 0; nc < 8; nc++) {
                int c0 = nc * 8 + 2 * tig, c1 = c0 + 1;
                if (c0 > r_lo) s[nc][0] = -1e30f;
                if (c1 > r_lo) s[nc][1] = -1e30f;
                if (c0 > r_hi) s[nc][2] = -1e30f;
                if (c1 > r_hi) s[nc][3] = -1e30f;
            }
        }

        float mx0 = -1e30f, mx1 = -1e30f;
        #pragma unroll
        for (int nc = 0; nc < 8; nc++) {
            mx0 = fmaxf(mx0, fmaxf(s[nc][0], s[nc][1]));
            mx1 = fmaxf(mx1, fmaxf(s[nc][2], s[nc][3]));
        }
        mx0 = fmaxf(mx0, __shfl_xor_sync(0xffffffffu, mx0, 1));
        mx0 = fmaxf(mx0, __shfl_xor_sync(0xffffffffu, mx0, 2));
        mx1 = fmaxf(mx1, __shfl_xor_sync(0xffffffffu, mx1, 1));
        mx1 = fmaxf(mx1, __shfl_xor_sync(0xffffffffu, mx1, 2));

        float mn0 = fmaxf(m0, mx0), mn1 = fmaxf(m1, mx1);
        float al0 = __expf(m0 - mn0), al1 = __expf(m1 - mn1);

        float rs0 = 0.0f, rs1 = 0.0f;
        #pragma unroll
        for (int nc = 0; nc < 8; nc++) {
            float p0 = __expf(s[nc][0] - mn0);
            float p1 = __expf(s[nc][1] - mn0);
            float p2 = __expf(s[nc][2] - mn1);
            float p3 = __expf(s[nc][3] - mn1);
            rs0 += p0 + p1;
            rs1 += p2 + p3;
            uint2 lo = make_uint2(f2tf(p0), f2tf(p1));
            uint2 hi = make_uint2(f2tf(p2), f2tf(p3));
            *(uint2*)&Ps[(row0 + g) * QP + nc * 8 + 2 * tig]     = lo;
            *(uint2*)&Ps[(row0 + g + 8) * QP + nc * 8 + 2 * tig] = hi;
        }
        rs0 += __shfl_xor_sync(0xffffffffu, rs0, 1);
        rs0 += __shfl_xor_sync(0xffffffffu, rs0, 2);
        rs1 += __shfl_xor_sync(0xffffffffu, rs1, 1);
        rs1 += __shfl_xor_sync(0xffffffffu, rs1, 2);

        l0 = l0 * al0 + rs0;
        l1 = l1 * al1 + rs1;
        m0 = mn0;
        m1 = mn1;
        #pragma unroll
        for (int nc = 0; nc < 8; nc++) {
            o[nc][0] *= al0; o[nc][1] *= al0;
            o[nc][2] *= al1; o[nc][3] *= al1;
        }
        __syncwarp();  // Ps rows are warp-private

        // ---- O += P @ V ----
        #pragma unroll
        for (int kc = 0; kc < 8; kc++) {
            unsigned a[4];
            a[0] = Ps[(row0 + g) * QP + kc * 8 + tig];
            a[1] = Ps[(row0 + g + 8) * QP + kc * 8 + tig];
            a[2] = Ps[(row0 + g) * QP + kc * 8 + tig + 4];
            a[3] = Ps[(row0 + g + 8) * QP + kc * 8 + tig + 4];
            #pragma unroll
            for (int nc = 0; nc < 8; nc++) {
                unsigned b[2];
                b[0] = Vc[(kc * 8 + tig) * VP + nc * 8 + g];
                b[1] = Vc[(kc * 8 + tig + 4) * VP + nc * 8 + g];
                mma_tf32(o[nc], a, b);
            }
        }
    }

    // Normalize, round to tf32 bits (feeds out-proj), write ctx
    float inv0 = 1.0f / l0, inv1 = 1.0f / l1;
    #pragma unroll
    for (int nc = 0; nc < 8; nc++) {
        int col = h * HDIM + nc * 8 + 2 * tig;
        int r_lo = qb * 64 + row0 + g;
        uint2 lo = make_uint2(f2tf(o[nc][0] * inv0), f2tf(o[nc][1] * inv0));
        uint2 hi = make_uint2(f2tf(o[nc][2] * inv1), f2tf(o[nc][3] * inv1));
        *(uint2*)&g_ctx[(size_t)r_lo * DMODEL + col]       = lo;
        *(uint2*)&g_ctx[(size_t)(r_lo + 8) * DMODEL + col] = hi;
    }
}

// ---------------------------------------------------------------------------
extern "C" void kernel_launch(void* const* d_in, const int* in_sizes, int n_in,
                              void* d_out, int out_size) {
    (void)in_sizes; (void)n_in; (void)out_size;
    const float* x     = (const float*)d_in[0];
    const float* w_qkv = (const float*)d_in[1];
    const float* b_qkv = (const float*)d_in[2];
    const float* w_out = (const float*)d_in[3];
    const float* b_out = (const float*)d_in[4];
    float* out = (float*)d_out;

    float *qkv_ptr, *ctx_ptr, *xtf_ptr, *wqkv_ptr, *wout_ptr;
    cudaGetSymbolAddress((void**)&qkv_ptr,  g_qkv);
    cudaGetSymbolAddress((void**)&ctx_ptr,  g_ctx);
    cudaGetSymbolAddress((void**)&xtf_ptr,  g_x_tf);
    cudaGetSymbolAddress((void**)&wqkv_ptr, g_wqkv_tf);
    cudaGetSymbolAddress((void**)&wout_ptr, g_wout_tf);

    const int GEMM_SMEM = 2 * STG_TOT * (int)sizeof(float);                      // 37888
    const int ATTN_SMEM = (64 * QP + 2 * 64 * QP + 2 * 64 * VP) * (int)sizeof(unsigned); // 89088
    static bool attr_set = false;
    if (!attr_set) {
        cudaFuncSetAttribute(gemm_tf32_kernel,
                             cudaFuncAttributeMaxDynamicSharedMemorySize, GEMM_SMEM);
        cudaFuncSetAttribute(attn_tf32_kernel,
                             cudaFuncAttributeMaxDynamicSharedMemorySize, ATTN_SMEM);
        attr_set = true;
    }

    // 0) Pre-round inputs to tf32 bit patterns
    round_tf32_kernel<<<(SEQ * DMODEL / 4 + 255) / 256, 256>>>(x, xtf_ptr, SEQ * DMODEL / 4);
    round_tf32_kernel<<<(DMODEL * QKV_N / 4 + 255) / 256, 256>>>(w_qkv, wqkv_ptr, DMODEL * QKV_N / 4);
    round_tf32_kernel<<<(DMODEL * DMODEL / 4 + 255) / 256, 256>>>(w_out, wout_ptr, DMODEL * DMODEL / 4);

    // 1) QKV projection (output tf32-rounded)
    gemm_tf32_kernel<<<dim3(QKV_N / 128, SEQ / 128), 256, GEMM_SMEM>>>(
        xtf_ptr, wqkv_ptr, b_qkv, qkv_ptr, SEQ, QKV_N, DMODEL, 1);

    // 2) Causal attention (output tf32-rounded)
    attn_tf32_kernel<<<dim3(SEQ / 64, NHEADS), 128, ATTN_SMEM>>>();

    // 3) Output projection (full fp32 output)
    gemm_tf32_kernel<<<dim3(DMODEL / 128, SEQ / 128), 256, GEMM_SMEM>>>(
        ctx_ptr, wout_ptr, b_out, out, SEQ, DMODEL, DMODEL, 0);
}

// round 8
// speedup vs baseline: 1.3138x; 1.1509x over previous
#include <cuda_runtime.h>

#define SEQ 4096
#define DMODEL 1024
#define NHEADS 16
#define HDIM 64
#define QKV_N 3072

// Scratch (static device arrays — no allocation)
__device__ float g_qkv[SEQ * QKV_N];    // q|k|v, tf32-rounded bits
__device__ float g_ctx[SEQ * DMODEL];   // tf32-rounded bits
__device__ float g_x_tf[SEQ * DMODEL];          // pre-rounded x
__device__ float g_wqkv_tf[DMODEL * QKV_N];     // pre-rounded w_qkv
__device__ float g_wout_tf[DMODEL * DMODEL];    // pre-rounded w_out

// ---------------------------------------------------------------------------
// helpers
// ---------------------------------------------------------------------------
__device__ __forceinline__ unsigned f2tf(float f) {
    unsigned u;
    asm("cvt.rna.tf32.f32 %0, %1;" : "=r"(u) : "f"(f));
    return u;
}

__device__ __forceinline__ void mma_tf32(float c[4], const unsigned a[4], const unsigned b[2]) {
    asm volatile(
        "mma.sync.aligned.m16n8k8.row.col.f32.tf32.tf32.f32 "
        "{%0,%1,%2,%3},{%4,%5,%6,%7},{%8,%9},{%0,%1,%2,%3};"
        : "+f"(c[0]), "+f"(c[1]), "+f"(c[2]), "+f"(c[3])
        : "r"(a[0]), "r"(a[1]), "r"(a[2]), "r"(a[3]), "r"(b[0]), "r"(b[1]));
}

__device__ __forceinline__ void cp16(void* dst_smem, const void* src_gmem) {
    unsigned d = (unsigned)__cvta_generic_to_shared(dst_smem);
    asm volatile("cp.async.cg.shared.global [%0], [%1], 16;" :: "r"(d), "l"(src_gmem));
}
#define CP_COMMIT() asm volatile("cp.async.commit_group;")
#define CP_WAIT0()  asm volatile("cp.async.wait_group 0;")

// Pre-round fp32 -> tf32 bit pattern (elementwise, float4)
__global__ void round_tf32_kernel(const float* __restrict__ in,
                                  float* __restrict__ out, int n4) {
    int i = blockIdx.x * blockDim.x + threadIdx.x;
    if (i >= n4) return;
    float4 v = ((const float4*)in)[i];
    uint4 u;
    u.x = f2tf(v.x); u.y = f2tf(v.y); u.z = f2tf(v.z); u.w = f2tf(v.w);
    ((uint4*)out)[i] = u;
}

// ---------------------------------------------------------------------------
// TF32 tensor-core GEMM (R2 structure — measured best at 205us for QKV):
// C[M,N] = A[M,K] @ B[K,N] + bias[N];  A,B pre-rounded to tf32 bits.
// BM=128, BN=128, BK=32. 256 threads = 8 warps (4m x 2n); warp tile 32x64.
// Two barriers per k-tile, no prefetch (empirically fastest variant).
// ---------------------------------------------------------------------------
#define GAP 36   // A smem pitch: (4g+tig) unique mod 32; 36 words = 144B (16B-mult)
#define GBP 136  // B smem pitch: (8tig+g) unique mod 32; 544B (16B-mult)

__global__ __launch_bounds__(256) void gemm_tf32_kernel(
    const float* __restrict__ A, const float* __restrict__ B,
    const float* __restrict__ bias, float* __restrict__ C,
    int M, int N, int K, int round_out) {
    const int BM = 128, BK = 32;
    __shared__ unsigned As[BM][GAP];     // [m][k]
    __shared__ unsigned Bs[BK][GBP];     // [k][n]

    int tid = threadIdx.x;
    int wid = tid >> 5, lane = tid & 31;
    int g = lane >> 2, tig = lane & 3;
    int warp_m = wid >> 1, warp_n = wid & 1;
    int bm = blockIdx.y * 128, bn = blockIdx.x * 128;

    float acc[2][8][4];
    #pragma unroll
    for (int mc = 0; mc < 2; mc++)
        #pragma unroll
        for (int nc = 0; nc < 8; nc++)
            #pragma unroll
            for (int i = 0; i < 4; i++) acc[mc][nc][i] = 0.0f;

    for (int k0 = 0; k0 < K; k0 += BK) {
        __syncthreads();
        // A tile: 128 x 32 = 1024 float4 (raw bits, STS.128)
        #pragma unroll
        for (int i = 0; i < 4; i++) {
            int linear = tid + i * 256;
            int r  = linear >> 3;          // 0..127
            int c4 = (linear & 7) * 4;     // 0..28
            uint4 v = *(const uint4*)&A[(size_t)(bm + r) * K + k0 + c4];
            *(uint4*)&As[r][c4] = v;
        }
        // B tile: 32 x 128 = 1024 float4
        #pragma unroll
        for (int i = 0; i < 4; i++) {
            int linear = tid + i * 256;
            int r  = linear >> 5;          // 0..31
            int c4 = (linear & 31) * 4;    // 0..124
            uint4 v = *(const uint4*)&B[(size_t)(k0 + r) * N + bn + c4];
            *(uint4*)&Bs[r][c4] = v;
        }
        __syncthreads();

        #pragma unroll
        for (int kc = 0; kc < 4; kc++) {
            unsigned a[2][4];
            #pragma unroll
            for (int mc = 0; mc < 2; mc++) {
                int row = warp_m * 32 + mc * 16;
                a[mc][0] = As[row + g][kc * 8 + tig];
                a[mc][1] = As[row + g + 8][kc * 8 + tig];
                a[mc][2] = As[row + g][kc * 8 + tig + 4];
                a[mc][3] = As[row + g + 8][kc * 8 + tig + 4];
            }
            #pragma unroll
            for (int nc = 0; nc < 8; nc++) {
                unsigned b[2];
                int col = warp_n * 64 + nc * 8 + g;
                b[0] = Bs[kc * 8 + tig][col];
                b[1] = Bs[kc * 8 + tig + 4][col];
                mma_tf32(acc[0][nc], a[0], b);
                mma_tf32(acc[1][nc], a[1], b);
            }
        }
    }

    // Epilogue: bias + (optional tf32 rounding) + store
    #pragma unroll
    for (int nc = 0; nc < 8; nc++) {
        int col = bn + warp_n * 64 + nc * 8 + 2 * tig;
        float bv0 = bias[col], bv1 = bias[col + 1];
        #pragma unroll
        for (int mc = 0; mc < 2; mc++) {
            int row = bm + warp_m * 32 + mc * 16 + g;
            float v00 = acc[mc][nc][0] + bv0, v01 = acc[mc][nc][1] + bv1;
            float v10 = acc[mc][nc][2] + bv0, v11 = acc[mc][nc][3] + bv1;
            if (round_out) {
                v00 = __uint_as_float(f2tf(v00)); v01 = __uint_as_float(f2tf(v01));
                v10 = __uint_as_float(f2tf(v10)); v11 = __uint_as_float(f2tf(v11));
            }
            *(float2*)&C[(size_t)row * N + col]       = make_float2(v00, v01);
            *(float2*)&C[(size_t)(row + 8) * N + col] = make_float2(v10, v11);
        }
    }
}

// ---------------------------------------------------------------------------
// Flash attention (causal), warp tf32 mma, cp.async double-buffered K/V,
// Q fragments in registers. One CTA per (q-block 64, head). 128 threads.
// (R6 version — measured best)
// ---------------------------------------------------------------------------
#define QP 68
#define VP 72

__global__ __launch_bounds__(128) void attn_tf32_kernel() {
    extern __shared__ unsigned sm[];
    unsigned* Ps = sm;                  // [64][68]
    unsigned* Ks = Ps + 64 * QP;        // [2][64][68]
    unsigned* Vs = Ks + 2 * 64 * QP;    // [2][64][72]

    int qb = gridDim.x - 1 - blockIdx.x;
    int h  = blockIdx.y;
    int tid = threadIdx.x;
    int wid = tid >> 5, lane = tid & 31;
    int g = lane >> 2, tig = lane & 3;
    int row0 = wid * 16;

    const int k_off = DMODEL + h * HDIM;
    const int v_off = 2 * DMODEL + h * HDIM;

    auto cp_kv = [&](int jb, int buf) {
        unsigned* Kd = Ks + buf * 64 * QP;
        unsigned* Vd = Vs + buf * 64 * VP;
        #pragma unroll
        for (int i = 0; i < 8; i++) {
            int linear = tid + i * 128;
            int r  = linear >> 4;
            int c4 = (linear & 15) * 4;
            size_t grow = (size_t)(jb * 64 + r) * QKV_N;
            cp16(&Kd[r * QP + c4], &g_qkv[grow + k_off + c4]);
            cp16(&Vd[r * VP + c4], &g_qkv[grow + v_off + c4]);
        }
    };

    cp_kv(0, 0);
    CP_COMMIT();

    unsigned qf[8][4];
    {
        const float* Qb = g_qkv + (size_t)(qb * 64) * QKV_N + h * HDIM;
        #pragma unroll
        for (int kc = 0; kc < 8; kc++) {
            qf[kc][0] = __float_as_uint(Qb[(size_t)(row0 + g) * QKV_N + kc * 8 + tig]);
            qf[kc][1] = __float_as_uint(Qb[(size_t)(row0 + g + 8) * QKV_N + kc * 8 + tig]);
            qf[kc][2] = __float_as_uint(Qb[(size_t)(row0 + g) * QKV_N + kc * 8 + tig + 4]);
            qf[kc][3] = __float_as_uint(Qb[(size_t)(row0 + g + 8) * QKV_N + kc * 8 + tig + 4]);
        }
    }

    float o[8][4];
    #pragma unroll
    for (int nc = 0; nc < 8; nc++)
        #pragma unroll
        for (int i = 0; i < 4; i++) o[nc][i] = 0.0f;
    float m0 = -1e30f, m1 = -1e30f, l0 = 0.0f, l1 = 0.0f;

    for (int jb = 0; jb <= qb; jb++) {
        int buf = jb & 1;
        CP_WAIT0();
        __syncthreads();

        if (jb < qb) { cp_kv(jb + 1, buf ^ 1); CP_COMMIT(); }

        const unsigned* Kc = Ks + buf * 64 * QP;
        const unsigned* Vc = Vs + buf * 64 * VP;

        // ---- S = Q @ K^T ----
        float s[8][4];
        #pragma unroll
        for (int nc = 0; nc < 8; nc++)
            #pragma unroll
            for (int i = 0; i < 4; i++) s[nc][i] = 0.0f;

        #pragma unroll
        for (int kc = 0; kc < 8; kc++) {
            #pragma unroll
            for (int nc = 0; nc < 8; nc++) {
                unsigned b[2];
                b[0] = Kc[(nc * 8 + g) * QP + kc * 8 + tig];
                b[1] = Kc[(nc * 8 + g) * QP + kc * 8 + tig + 4];
                mma_tf32(s[nc], qf[kc], b);
            }
        }

        #pragma unroll
        for (int nc = 0; nc < 8; nc++)
            #pragma unroll
            for (int i = 0; i < 4; i++) s[nc][i] *= 0.125f;

        if (jb == qb) {
            int r_lo = row0 + g, r_hi = row0 + g + 8;
            #pragma unroll
            for (int nc = 0; nc < 8; nc++) {
                int c0 = nc * 8 + 2 * tig, c1 = c0 + 1;
                if (c0 > r_lo) s[nc][0] = -1e30f;
                if (c1 > r_lo) s[nc][1] = -1e30f;
                if (c0 > r_hi) s[nc][2] = -1e30f;
                if (c1 > r_hi) s[nc][3] = -1e30f;
            }
        }

        float mx0 = -1e30f, mx1 = -1e30f;
        #pragma unroll
        for (int nc = 0; nc < 8; nc++) {
            mx0 = fmaxf(mx0, fmaxf(s[nc][0], s[nc][1]));
            mx1 = fmaxf(mx1, fmaxf(s[nc][2], s[nc][3]));
        }
        mx0 = fmaxf(mx0, __shfl_xor_sync(0xffffffffu, mx0, 1));
        mx0 = fmaxf(mx0, __shfl_xor_sync(0xffffffffu, mx0, 2));
        mx1 = fmaxf(mx1, __shfl_xor_sync(0xffffffffu, mx1, 1));
        mx1 = fmaxf(mx1, __shfl_xor_sync(0xffffffffu, mx1, 2));

        float mn0 = fmaxf(m0, mx0), mn1 = fmaxf(m1, mx1);
        float al0 = __expf(m0 - mn0), al1 = __expf(m1 - mn1);

        float rs0 = 0.0f, rs1 = 0.0f;
        #pragma unroll
        for (int nc = 0; nc < 8; nc++) {
            float p0 = __expf(s[nc][0] - mn0);
            float p1 = __expf(s[nc][1] - mn0);
            float p2 = __expf(s[nc][2] - mn1);
            float p3 = __expf(s[nc][3] - mn1);
            rs0 += p0 + p1;
            rs1 += p2 + p3;
            uint2 lo = make_uint2(f2tf(p0), f2tf(p1));
            uint2 hi = make_uint2(f2tf(p2), f2tf(p3));
            *(uint2*)&Ps[(row0 + g) * QP + nc * 8 + 2 * tig]     = lo;
            *(uint2*)&Ps[(row0 + g + 8) * QP + nc * 8 + 2 * tig] = hi;
        }
        rs0 += __shfl_xor_sync(0xffffffffu, rs0, 1);
        rs0 += __shfl_xor_sync(0xffffffffu, rs0, 2);
        rs1 += __shfl_xor_sync(0xffffffffu, rs1, 1);
        rs1 += __shfl_xor_sync(0xffffffffu, rs1, 2);

        l0 = l0 * al0 + rs0;
        l1 = l1 * al1 + rs1;
        m0 = mn0;
        m1 = mn1;
        #pragma unroll
        for (int nc = 0; nc < 8; nc++) {
            o[nc][0] *= al0; o[nc][1] *= al0;
            o[nc][2] *= al1; o[nc][3] *= al1;
        }
        __syncwarp();

        // ---- O += P @ V ----
        #pragma unroll
        for (int kc = 0; kc < 8; kc++) {
            unsigned a[4];
            a[0] = Ps[(row0 + g) * QP + kc * 8 + tig];
            a[1] = Ps[(row0 + g + 8) * QP + kc * 8 + tig];
            a[2] = Ps[(row0 + g) * QP + kc * 8 + tig + 4];
            a[3] = Ps[(row0 + g + 8) * QP + kc * 8 + tig + 4];
            #pragma unroll
            for (int nc = 0; nc < 8; nc++) {
                unsigned b[2];
                b[0] = Vc[(kc * 8 + tig) * VP + nc * 8 + g];
                b[1] = Vc[(kc * 8 + tig + 4) * VP + nc * 8 + g];
                mma_tf32(o[nc], a, b);
            }
        }
    }

    float inv0 = 1.0f / l0, inv1 = 1.0f / l1;
    #pragma unroll
    for (int nc = 0; nc < 8; nc++) {
        int col = h * HDIM + nc * 8 + 2 * tig;
        int r_lo = qb * 64 + row0 + g;
        uint2 lo = make_uint2(f2tf(o[nc][0] * inv0), f2tf(o[nc][1] * inv0));
        uint2 hi = make_uint2(f2tf(o[nc][2] * inv1), f2tf(o[nc][3] * inv1));
        *(uint2*)&g_ctx[(size_t)r_lo * DMODEL + col]       = lo;
        *(uint2*)&g_ctx[(size_t)(r_lo + 8) * DMODEL + col] = hi;
    }
}

// ---------------------------------------------------------------------------
extern "C" void kernel_launch(void* const* d_in, const int* in_sizes, int n_in,
                              void* d_out, int out_size) {
    (void)in_sizes; (void)n_in; (void)out_size;
    const float* x     = (const float*)d_in[0];
    const float* w_qkv = (const float*)d_in[1];
    const float* b_qkv = (const float*)d_in[2];
    const float* w_out = (const float*)d_in[3];
    const float* b_out = (const float*)d_in[4];
    float* out = (float*)d_out;

    float *qkv_ptr, *ctx_ptr, *xtf_ptr, *wqkv_ptr, *wout_ptr;
    cudaGetSymbolAddress((void**)&qkv_ptr,  g_qkv);
    cudaGetSymbolAddress((void**)&ctx_ptr,  g_ctx);
    cudaGetSymbolAddress((void**)&xtf_ptr,  g_x_tf);
    cudaGetSymbolAddress((void**)&wqkv_ptr, g_wqkv_tf);
    cudaGetSymbolAddress((void**)&wout_ptr, g_wout_tf);

    const int ATTN_SMEM = (64 * QP + 2 * 64 * QP + 2 * 64 * VP) * (int)sizeof(unsigned); // 89088
    static bool attr_set = false;
    if (!attr_set) {
        cudaFuncSetAttribute(attn_tf32_kernel,
                             cudaFuncAttributeMaxDynamicSharedMemorySize, ATTN_SMEM);
        attr_set = true;
    }

    // 0) Pre-round inputs to tf32 bit patterns
    round_tf32_kernel<<<(SEQ * DMODEL / 4 + 255) / 256, 256>>>(x, xtf_ptr, SEQ * DMODEL / 4);
    round_tf32_kernel<<<(DMODEL * QKV_N / 4 + 255) / 256, 256>>>(w_qkv, wqkv_ptr, DMODEL * QKV_N / 4);
    round_tf32_kernel<<<(DMODEL * DMODEL / 4 + 255) / 256, 256>>>(w_out, wout_ptr, DMODEL * DMODEL / 4);

    // 1) QKV projection (output tf32-rounded)
    gemm_tf32_kernel<<<dim3(QKV_N / 128, SEQ / 128), 256>>>(
        xtf_ptr, wqkv_ptr, b_qkv, qkv_ptr, SEQ, QKV_N, DMODEL, 1);

    // 2) Causal attention (output tf32-rounded)
    attn_tf32_kernel<<<dim3(SEQ / 64, NHEADS), 128, ATTN_SMEM>>>();

    // 3) Output projection (full fp32 output)
    gemm_tf32_kernel<<<dim3(DMODEL / 128, SEQ / 128), 256>>>(
        ctx_ptr, wout_ptr, b_out, out, SEQ, DMODEL, DMODEL, 0);
}

// round 11
// speedup vs baseline: 1.6222x; 1.2347x over previous
#include <cuda_runtime.h>
#include <cuda_fp16.h>

#define SEQ 4096
#define DMODEL 1024
#define NHEADS 16
#define HDIM 64
#define QKV_N 3072

// Scratch (static device arrays — no allocation)
__device__ __half g_qkv_h[SEQ * QKV_N];   // q|k|v fp16
__device__ __half g_ctx_h[SEQ * DMODEL];  // ctx fp16
__device__ __half g_x_h[SEQ * DMODEL];            // x fp16
__device__ __half g_wqkvT_h[QKV_N * DMODEL];      // w_qkv^T [N][K] fp16
__device__ __half g_woutT_h[DMODEL * DMODEL];     // w_out^T [N][K] fp16

// ---------------------------------------------------------------------------
// helpers
// ---------------------------------------------------------------------------
__device__ __forceinline__ void mma_f16(float c[4], const unsigned a[4], const unsigned b[2]) {
    asm volatile(
        "mma.sync.aligned.m16n8k16.row.col.f32.f16.f16.f32 "
        "{%0,%1,%2,%3},{%4,%5,%6,%7},{%8,%9},{%0,%1,%2,%3};"
        : "+f"(c[0]), "+f"(c[1]), "+f"(c[2]), "+f"(c[3])
        : "r"(a[0]), "r"(a[1]), "r"(a[2]), "r"(a[3]), "r"(b[0]), "r"(b[1]));
}

__device__ __forceinline__ void cp16(void* dst_smem, const void* src_gmem) {
    unsigned d = (unsigned)__cvta_generic_to_shared(dst_smem);
    asm volatile("cp.async.cg.shared.global [%0], [%1], 16;" :: "r"(d), "l"(src_gmem));
}
#define CP_COMMIT() asm volatile("cp.async.commit_group;")
#define CP_WAIT0()  asm volatile("cp.async.wait_group 0;")

// fp32 -> fp16 elementwise (float4 granularity)
__global__ void f2h_kernel(const float* __restrict__ in, __half* __restrict__ out, int n4) {
    int i = blockIdx.x * blockDim.x + threadIdx.x;
    if (i >= n4) return;
    float4 v = ((const float4*)in)[i];
    ((__half2*)out)[2 * i]     = __floats2half2_rn(v.x, v.y);
    ((__half2*)out)[2 * i + 1] = __floats2half2_rn(v.z, v.w);
}

// out[C][R] (fp16) = in[R][C]^T
__global__ void transpose_h_kernel(const float* __restrict__ in,
                                   __half* __restrict__ out, int R, int C) {
    __shared__ float t[32][33];
    int c0 = blockIdx.x * 32, r0 = blockIdx.y * 32;
    int tx = threadIdx.x, ty = threadIdx.y;
    #pragma unroll
    for (int i = 0; i < 4; i++)
        t[ty + i * 8][tx] = in[(size_t)(r0 + ty + i * 8) * C + c0 + tx];
    __syncthreads();
    #pragma unroll
    for (int i = 0; i < 4; i++)
        out[(size_t)(c0 + ty + i * 8) * R + r0 + tx] = __float2half(t[tx][ty + i * 8]);
}

// ---------------------------------------------------------------------------
// FP16 tensor-core GEMM (R2 structure): C[M,N] = A[M,K] @ BT[N,K]^T + bias
// BM=BN=128, BK=32. 256 threads = 8 warps (4m x 2n); warp tile 32x64.
// Each thread loads 16 halves (2 x uint4) of A and of B per k-tile.
// ---------------------------------------------------------------------------
#define PHG 40   // smem pitch in halves; word-pitch 20: (20g+tig) distinct mod 32

__global__ __launch_bounds__(256) void gemm_h_kernel(
    const __half* __restrict__ A, const __half* __restrict__ BT,
    const float* __restrict__ bias, void* __restrict__ Cout,
    int M, int N, int K, int half_out) {
    __shared__ __half As[128 * PHG];
    __shared__ __half Bs[128 * PHG];

    int tid = threadIdx.x;
    int wid = tid >> 5, lane = tid & 31;
    int g = lane >> 2, tig = lane & 3;
    int warp_m = wid >> 1, warp_n = wid & 1;
    int bm = blockIdx.y * 128, bn = blockIdx.x * 128;

    int lr = tid >> 1, lc = (tid & 1) * 16;   // each thread: 16 halves = 2 uint4
    const __half* Agp = A + (size_t)(bm + lr) * K + lc;
    const __half* Bgp = BT + (size_t)(bn + lr) * K + lc;

    float acc[2][8][4];
    #pragma unroll
    for (int mc = 0; mc < 2; mc++)
        #pragma unroll
        for (int nc = 0; nc < 8; nc++)
            #pragma unroll
            for (int i = 0; i < 4; i++) acc[mc][nc][i] = 0.0f;

    for (int k0 = 0; k0 < K; k0 += 32) {
        __syncthreads();
        *(uint4*)&As[lr * PHG + lc]     = *(const uint4*)(Agp + k0);
        *(uint4*)&As[lr * PHG + lc + 8] = *(const uint4*)(Agp + k0 + 8);
        *(uint4*)&Bs[lr * PHG + lc]     = *(const uint4*)(Bgp + k0);
        *(uint4*)&Bs[lr * PHG + lc + 8] = *(const uint4*)(Bgp + k0 + 8);
        __syncthreads();

        #pragma unroll
        for (int kc = 0; kc < 2; kc++) {
            unsigned a[2][4];
            #pragma unroll
            for (int mc = 0; mc < 2; mc++) {
                int row = warp_m * 32 + mc * 16;
                a[mc][0] = *(const unsigned*)&As[(row + g) * PHG + kc * 16 + 2 * tig];
                a[mc][1] = *(const unsigned*)&As[(row + g + 8) * PHG + kc * 16 + 2 * tig];
                a[mc][2] = *(const unsigned*)&As[(row + g) * PHG + kc * 16 + 2 * tig + 8];
                a[mc][3] = *(const unsigned*)&As[(row + g + 8) * PHG + kc * 16 + 2 * tig + 8];
            }
            #pragma unroll
            for (int nc = 0; nc < 8; nc++) {
                int col = warp_n * 64 + nc * 8 + g;
                unsigned b[2];
                b[0] = *(const unsigned*)&Bs[col * PHG + kc * 16 + 2 * tig];
                b[1] = *(const unsigned*)&Bs[col * PHG + kc * 16 + 2 * tig + 8];
                mma_f16(acc[0][nc], a[0], b);
                mma_f16(acc[1][nc], a[1], b);
            }
        }
    }

    // Epilogue
    #pragma unroll
    for (int nc = 0; nc < 8; nc++) {
        int col = bn + warp_n * 64 + nc * 8 + 2 * tig;
        float bv0 = bias[col], bv1 = bias[col + 1];
        #pragma unroll
        for (int mc = 0; mc < 2; mc++) {
            int row = bm + warp_m * 32 + mc * 16 + g;
            float v00 = acc[mc][nc][0] + bv0, v01 = acc[mc][nc][1] + bv1;
            float v10 = acc[mc][nc][2] + bv0, v11 = acc[mc][nc][3] + bv1;
            if (half_out) {
                __half* Ch = (__half*)Cout;
                *(__half2*)&Ch[(size_t)row * N + col]       = __floats2half2_rn(v00, v01);
                *(__half2*)&Ch[(size_t)(row + 8) * N + col] = __floats2half2_rn(v10, v11);
            } else {
                float* Cf = (float*)Cout;
                *(float2*)&Cf[(size_t)row * N + col]       = make_float2(v00, v01);
                *(float2*)&Cf[(size_t)(row + 8) * N + col] = make_float2(v10, v11);
            }
        }
    }
}

// ---------------------------------------------------------------------------
// Flash attention (causal), fp16 m16n8k16 mma.
// One CTA per (q-block 64, head). 128 threads = 4 warps.
// K: cp.async double-buffered [kpos][hd]. V: LDG.128 x2 + packed half2 STS
// into [hd][kpos] (transposed -> clean B-frags). P: half2 pairs. Q: regs.
// All tiles share word-pitch PW=36 (=4 mod 32 -> 4g+tig conflict-free).
// ---------------------------------------------------------------------------
#define PW 36

__global__ __launch_bounds__(128) void attn_h_kernel() {
    extern __shared__ unsigned sm[];
    unsigned* Ps = sm;                 // [64 rows][36 words] (kpos pairs)
    unsigned* Ks = Ps + 64 * PW;       // [2][64 kpos][36 words] (hd halves)
    unsigned* Vs = Ks + 2 * 64 * PW;   // [2][64 hd][36 words] (kpos pairs)

    int qb = gridDim.x - 1 - blockIdx.x;  // longest CTAs first
    int h  = blockIdx.y;
    int tid = threadIdx.x;
    int wid = tid >> 5, lane = tid & 31;
    int g = lane >> 2, tig = lane & 3;
    int row0 = wid * 16;

    const int k_off = DMODEL + h * HDIM;
    const int v_off = 2 * DMODEL + h * HDIM;

    // K loader (cp.async): 64 rows x 64 halves (128B/row), pitch 144B
    auto cp_k = [&](int jb, int buf) {
        char* Kd = (char*)(Ks + buf * 64 * PW);
        #pragma unroll
        for (int i = 0; i < 4; i++) {
            int linear = tid + i * 128;
            int r  = linear >> 3;
            int c8 = (linear & 7) * 8;     // half offset
            cp16(Kd + r * 144 + c8 * 2,
                 &g_qkv_h[(size_t)(jb * 64 + r) * QKV_N + k_off + c8]);
        }
    };

    // V loader: warp wid covers hd [wid*16, wid*16+16); lane owns kpos pair
    // (2*lane, 2*lane+1). Each row needs 16 halves = 2 x uint4.
    int vc0 = wid * 16, vp = lane;
    uint4 vr[4];   // [row0 lo8, row0 hi8, row1 lo8, row1 hi8]
    auto v_ldg = [&](int jb) {
        const __half* p0 = &g_qkv_h[(size_t)(jb * 64 + 2 * vp) * QKV_N + v_off + vc0];
        vr[0] = *(const uint4*)p0;
        vr[1] = *(const uint4*)(p0 + 8);
        vr[2] = *(const uint4*)(p0 + QKV_N);
        vr[3] = *(const uint4*)(p0 + QKV_N + 8);
    };
    auto v_sts = [&](int buf) {
        unsigned* Vd = Vs + buf * 64 * PW;
        const __half* r0lo = (const __half*)&vr[0];
        const __half* r0hi = (const __half*)&vr[1];
        const __half* r1lo = (const __half*)&vr[2];
        const __half* r1hi = (const __half*)&vr[3];
        #pragma unroll
        for (int j = 0; j < 8; j++) {
            __half2 w0 = __halves2half2(r0lo[j], r1lo[j]);
            Vd[(vc0 + j) * PW + vp] = *(unsigned*)&w0;
            __half2 w1 = __halves2half2(r0hi[j], r1hi[j]);
            Vd[(vc0 + 8 + j) * PW + vp] = *(unsigned*)&w1;
        }
    };

    cp_k(0, 0);
    CP_COMMIT();
    v_ldg(0);

    // Q fragments in registers (4 kc x 4 regs, each reg = 2 halves)
    unsigned qf[4][4];
    {
        const __half* Qb = g_qkv_h + (size_t)(qb * 64) * QKV_N + h * HDIM;
        #pragma unroll
        for (int kc = 0; kc < 4; kc++) {
            qf[kc][0] = *(const unsigned*)&Qb[(size_t)(row0 + g) * QKV_N + kc * 16 + 2 * tig];
            qf[kc][1] = *(const unsigned*)&Qb[(size_t)(row0 + g + 8) * QKV_N + kc * 16 + 2 * tig];
            qf[kc][2] = *(const unsigned*)&Qb[(size_t)(row0 + g) * QKV_N + kc * 16 + 2 * tig + 8];
            qf[kc][3] = *(const unsigned*)&Qb[(size_t)(row0 + g + 8) * QKV_N + kc * 16 + 2 * tig + 8];
        }
    }
    v_sts(0);

    float o[8][4];
    #pragma unroll
    for (int nc = 0; nc < 8; nc++)
        #pragma unroll
        for (int i = 0; i < 4; i++) o[nc][i] = 0.0f;
    float m0 = -1e30f, m1 = -1e30f, l0 = 0.0f, l1 = 0.0f;

    for (int jb = 0; jb <= qb; jb++) {
        int buf = jb & 1;
        CP_WAIT0();          // K[jb] landed
        __syncthreads();     // K cp.async + V STS visible; prev-iter reads done

        if (jb < qb) {
            cp_k(jb + 1, buf ^ 1);
            CP_COMMIT();
            v_ldg(jb + 1);   // LDG latency overlapped with S compute below
        }

        const unsigned* Kc = Ks + buf * 64 * PW;
        const unsigned* Vc = Vs + buf * 64 * PW;

        // ---- S = Q @ K^T ----
        float s[8][4];
        #pragma unroll
        for (int nc = 0; nc < 8; nc++)
            #pragma unroll
            for (int i = 0; i < 4; i++) s[nc][i] = 0.0f;

        #pragma unroll
        for (int kc = 0; kc < 4; kc++) {
            #pragma unroll
            for (int nc = 0; nc < 8; nc++) {
                unsigned b[2];
                b[0] = Kc[(nc * 8 + g) * PW + kc * 8 + tig];
                b[1] = Kc[(nc * 8 + g) * PW + kc * 8 + tig + 4];
                mma_f16(s[nc], qf[kc], b);
            }
        }

        #pragma unroll
        for (int nc = 0; nc < 8; nc++)
            #pragma unroll
            for (int i = 0; i < 4; i++) s[nc][i] *= 0.125f;

        if (jb == qb) {
            int r_lo = row0 + g, r_hi = row0 + g + 8;
            #pragma unroll
            for (int nc = 0; nc < 8; nc++) {
                int c0 = nc * 8 + 2 * tig, c1 = c0 + 1;
                if (c0 > r_lo) s[nc][0] = -1e30f;
                if (c1 > r_lo) s[nc][1] = -1e30f;
                if (c0 > r_hi) s[nc][2] = -1e30f;
                if (c1 > r_hi) s[nc][3] = -1e30f;
            }
        }

        // stash next V tile while regs are live
        if (jb < qb) v_sts(buf ^ 1);

        float mx0 = -1e30f, mx1 = -1e30f;
        #pragma unroll
        for (int nc = 0; nc < 8; nc++) {
            mx0 = fmaxf(mx0, fmaxf(s[nc][0], s[nc][1]));
            mx1 = fmaxf(mx1, fmaxf(s[nc][2], s[nc][3]));
        }
        mx0 = fmaxf(mx0, __shfl_xor_sync(0xffffffffu, mx0, 1));
        mx0 = fmaxf(mx0, __shfl_xor_sync(0xffffffffu, mx0, 2));
        mx1 = fmaxf(mx1, __shfl_xor_sync(0xffffffffu, mx1, 1));
        mx1 = fmaxf(mx1, __shfl_xor_sync(0xffffffffu, mx1, 2));

        float mn0 = fmaxf(m0, mx0), mn1 = fmaxf(m1, mx1);
        float al0 = __expf(m0 - mn0), al1 = __expf(m1 - mn1);

        float rs0 = 0.0f, rs1 = 0.0f;
        #pragma unroll
        for (int nc = 0; nc < 8; nc++) {
            float p0 = __expf(s[nc][0] - mn0);
            float p1 = __expf(s[nc][1] - mn0);
            float p2 = __expf(s[nc][2] - mn1);
            float p3 = __expf(s[nc][3] - mn1);
            rs0 += p0 + p1;
            rs1 += p2 + p3;
            __half2 lo = __floats2half2_rn(p0, p1);
            __half2 hi = __floats2half2_rn(p2, p3);
            Ps[(row0 + g) * PW + nc * 4 + tig]     = *(unsigned*)&lo;
            Ps[(row0 + g + 8) * PW + nc * 4 + tig] = *(unsigned*)&hi;
        }
        rs0 += __shfl_xor_sync(0xffffffffu, rs0, 1);
        rs0 += __shfl_xor_sync(0xffffffffu, rs0, 2);
        rs1 += __shfl_xor_sync(0xffffffffu, rs1, 1);
        rs1 += __shfl_xor_sync(0xffffffffu, rs1, 2);

        l0 = l0 * al0 + rs0;
        l1 = l1 * al1 + rs1;
        m0 = mn0;
        m1 = mn1;
        #pragma unroll
        for (int nc = 0; nc < 8; nc++) {
            o[nc][0] *= al0; o[nc][1] *= al0;
            o[nc][2] *= al1; o[nc][3] *= al1;
        }
        __syncwarp();   // Ps rows are warp-private

        // ---- O += P @ V ----
        #pragma unroll
        for (int kc = 0; kc < 4; kc++) {
            unsigned a[4];
            a[0] = Ps[(row0 + g) * PW + kc * 8 + tig];
            a[1] = Ps[(row0 + g + 8) * PW + kc * 8 + tig];
            a[2] = Ps[(row0 + g) * PW + kc * 8 + tig + 4];
            a[3] = Ps[(row0 + g + 8) * PW + kc * 8 + tig + 4];
            #pragma unroll
            for (int nc = 0; nc < 8; nc++) {
                unsigned b[2];
                b[0] = Vc[(nc * 8 + g) * PW + kc * 8 + tig];
                b[1] = Vc[(nc * 8 + g) * PW + kc * 8 + tig + 4];
                mma_f16(o[nc], a, b);
            }
        }
    }

    // Normalize, write ctx (fp16)
    float inv0 = 1.0f / l0, inv1 = 1.0f / l1;
    #pragma unroll
    for (int nc = 0; nc < 8; nc++) {
        int col = h * HDIM + nc * 8 + 2 * tig;
        int r_lo = qb * 64 + row0 + g;
        __half2 lo = __floats2half2_rn(o[nc][0] * inv0, o[nc][1] * inv0);
        __half2 hi = __floats2half2_rn(o[nc][2] * inv1, o[nc][3] * inv1);
        *(__half2*)&g_ctx_h[(size_t)r_lo * DMODEL + col]       = lo;
        *(__half2*)&g_ctx_h[(size_t)(r_lo + 8) * DMODEL + col] = hi;
    }
}

// ---------------------------------------------------------------------------
extern "C" void kernel_launch(void* const* d_in, const int* in_sizes, int n_in,
                              void* d_out, int out_size) {
    (void)in_sizes; (void)n_in; (void)out_size;
    const float* x     = (const float*)d_in[0];
    const float* w_qkv = (const float*)d_in[1];
    const float* b_qkv = (const float*)d_in[2];
    const float* w_out = (const float*)d_in[3];
    const float* b_out = (const float*)d_in[4];
    float* out = (float*)d_out;

    __half *qkv_ptr, *ctx_ptr, *xh_ptr, *wqkvT_ptr, *woutT_ptr;
    cudaGetSymbolAddress((void**)&qkv_ptr,   g_qkv_h);
    cudaGetSymbolAddress((void**)&ctx_ptr,   g_ctx_h);
    cudaGetSymbolAddress((void**)&xh_ptr,    g_x_h);
    cudaGetSymbolAddress((void**)&wqkvT_ptr, g_wqkvT_h);
    cudaGetSymbolAddress((void**)&woutT_ptr, g_woutT_h);

    const int ATTN_SMEM = 5 * 64 * PW * (int)sizeof(unsigned);   // 46080
    static bool attr_set = false;
    if (!attr_set) {
        cudaFuncSetAttribute(attn_h_kernel,
                             cudaFuncAttributeMaxDynamicSharedMemorySize, ATTN_SMEM);
        attr_set = true;
    }

    // 0) Convert inputs: x -> fp16; weights -> transposed fp16 [N][K]
    f2h_kernel<<<(SEQ * DMODEL / 4 + 255) / 256, 256>>>(x, xh_ptr, SEQ * DMODEL / 4);
    transpose_h_kernel<<<dim3(QKV_N / 32, DMODEL / 32), dim3(32, 8)>>>(
        w_qkv, wqkvT_ptr, DMODEL, QKV_N);
    transpose_h_kernel<<<dim3(DMODEL / 32, DMODEL / 32), dim3(32, 8)>>>(
        w_out, woutT_ptr, DMODEL, DMODEL);

    // 1) QKV projection (fp16 out)
    gemm_h_kernel<<<dim3(QKV_N / 128, SEQ / 128), 256>>>(
        xh_ptr, wqkvT_ptr, b_qkv, qkv_ptr, SEQ, QKV_N, DMODEL, 1);

    // 2) Causal attention
    attn_h_kernel<<<dim3(SEQ / 64, NHEADS), 128, ATTN_SMEM>>>();

    // 3) Output projection (fp32 out)
    gemm_h_kernel<<<dim3(DMODEL / 128, SEQ / 128), 256>>>(
        ctx_ptr, woutT_ptr, b_out, out, SEQ, DMODEL, DMODEL, 0);
}

// round 12
// speedup vs baseline: 1.7160x; 1.0578x over previous
#include <cuda_runtime.h>
#include <cuda_fp16.h>

#define SEQ 4096
#define DMODEL 1024
#define NHEADS 16
#define HDIM 64
#define QKV_N 3072

// Scratch (static device arrays — no allocation)
__device__ __half g_qkv_h[SEQ * QKV_N];   // q|k|v fp16
__device__ __half g_ctx_h[SEQ * DMODEL];  // ctx fp16
__device__ __half g_x_h[SEQ * DMODEL];            // x fp16
__device__ __half g_wqkvT_h[QKV_N * DMODEL];      // w_qkv^T [N][K] fp16
__device__ __half g_woutT_h[DMODEL * DMODEL];     // w_out^T [N][K] fp16

// ---------------------------------------------------------------------------
// helpers
// ---------------------------------------------------------------------------
__device__ __forceinline__ void mma_f16(float c[4], const unsigned a[4], const unsigned b[2]) {
    asm volatile(
        "mma.sync.aligned.m16n8k16.row.col.f32.f16.f16.f32 "
        "{%0,%1,%2,%3},{%4,%5,%6,%7},{%8,%9},{%0,%1,%2,%3};"
        : "+f"(c[0]), "+f"(c[1]), "+f"(c[2]), "+f"(c[3])
        : "r"(a[0]), "r"(a[1]), "r"(a[2]), "r"(a[3]), "r"(b[0]), "r"(b[1]));
}

__device__ __forceinline__ void ldsm_x4(unsigned r[4], unsigned addr) {
    asm volatile("ldmatrix.sync.aligned.m8n8.x4.shared.b16 {%0,%1,%2,%3}, [%4];"
                 : "=r"(r[0]), "=r"(r[1]), "=r"(r[2]), "=r"(r[3]) : "r"(addr));
}

__device__ __forceinline__ float ex2(float x) {
    float y;
    asm("ex2.approx.f32 %0, %1;" : "=f"(y) : "f"(x));
    return y;
}

__device__ __forceinline__ void cp16(void* dst_smem, const void* src_gmem) {
    unsigned d = (unsigned)__cvta_generic_to_shared(dst_smem);
    asm volatile("cp.async.cg.shared.global [%0], [%1], 16;" :: "r"(d), "l"(src_gmem));
}
#define CP_COMMIT() asm volatile("cp.async.commit_group;")
#define CP_WAIT0()  asm volatile("cp.async.wait_group 0;")

// fp32 -> fp16 elementwise (float4 granularity)
__global__ void f2h_kernel(const float* __restrict__ in, __half* __restrict__ out, int n4) {
    int i = blockIdx.x * blockDim.x + threadIdx.x;
    if (i >= n4) return;
    float4 v = ((const float4*)in)[i];
    ((__half2*)out)[2 * i]     = __floats2half2_rn(v.x, v.y);
    ((__half2*)out)[2 * i + 1] = __floats2half2_rn(v.z, v.w);
}

// out[C][R] (fp16) = in[R][C]^T
__global__ void transpose_h_kernel(const float* __restrict__ in,
                                   __half* __restrict__ out, int R, int C) {
    __shared__ float t[32][33];
    int c0 = blockIdx.x * 32, r0 = blockIdx.y * 32;
    int tx = threadIdx.x, ty = threadIdx.y;
    #pragma unroll
    for (int i = 0; i < 4; i++)
        t[ty + i * 8][tx] = in[(size_t)(r0 + ty + i * 8) * C + c0 + tx];
    __syncthreads();
    #pragma unroll
    for (int i = 0; i < 4; i++)
        out[(size_t)(c0 + ty + i * 8) * R + r0 + tx] = __float2half(t[tx][ty + i * 8]);
}

// ---------------------------------------------------------------------------
// FP16 tensor-core GEMM with ldmatrix fragment loads.
// C[M,N] = A[M,K] @ BT[N,K]^T + bias. BM=BN=128, BK=32. 256 threads = 8 warps.
// ---------------------------------------------------------------------------
#define PHG 40   // smem pitch in halves; 20 words: 20r mod 32 spans all banks

__global__ __launch_bounds__(256) void gemm_h_kernel(
    const __half* __restrict__ A, const __half* __restrict__ BT,
    const float* __restrict__ bias, void* __restrict__ Cout,
    int M, int N, int K, int half_out) {
    __shared__ __half As[128 * PHG];
    __shared__ __half Bs[128 * PHG];

    int tid = threadIdx.x;
    int wid = tid >> 5, lane = tid & 31;
    int g = lane >> 2, tig = lane & 3;
    int warp_m = wid >> 1, warp_n = wid & 1;
    int bm = blockIdx.y * 128, bn = blockIdx.x * 128;

    int lr = tid >> 1, lc = (tid & 1) * 16;   // each thread: 16 halves = 2 uint4
    const __half* Agp = A + (size_t)(bm + lr) * K + lc;
    const __half* Bgp = BT + (size_t)(bn + lr) * K + lc;

    // ldmatrix lane addressing: matrix index m = lane>>3, row-in-matrix = lane&7
    int lm = lane >> 3, lrw = lane & 7;
    unsigned a_addr[2], b_addr[4];
    #pragma unroll
    for (int mc = 0; mc < 2; mc++)
        a_addr[mc] = (unsigned)__cvta_generic_to_shared(
            &As[(warp_m * 32 + mc * 16 + (lm & 1) * 8 + lrw) * PHG + (lm >> 1) * 8]);
    #pragma unroll
    for (int j = 0; j < 4; j++)
        b_addr[j] = (unsigned)__cvta_generic_to_shared(
            &Bs[(warp_n * 64 + j * 16 + (lm >> 1) * 8 + lrw) * PHG + (lm & 1) * 8]);

    float acc[2][8][4];
    #pragma unroll
    for (int mc = 0; mc < 2; mc++)
        #pragma unroll
        for (int nc = 0; nc < 8; nc++)
            #pragma unroll
            for (int i = 0; i < 4; i++) acc[mc][nc][i] = 0.0f;

    for (int k0 = 0; k0 < K; k0 += 32) {
        __syncthreads();
        *(uint4*)&As[lr * PHG + lc]     = *(const uint4*)(Agp + k0);
        *(uint4*)&As[lr * PHG + lc + 8] = *(const uint4*)(Agp + k0 + 8);
        *(uint4*)&Bs[lr * PHG + lc]     = *(const uint4*)(Bgp + k0);
        *(uint4*)&Bs[lr * PHG + lc + 8] = *(const uint4*)(Bgp + k0 + 8);
        __syncthreads();

        #pragma unroll
        for (int kc = 0; kc < 2; kc++) {
            unsigned a[2][4];
            ldsm_x4(a[0], a_addr[0] + kc * 32);
            ldsm_x4(a[1], a_addr[1] + kc * 32);
            #pragma unroll
            for (int j = 0; j < 4; j++) {
                unsigned bb[4];
                ldsm_x4(bb, b_addr[j] + kc * 32);
                mma_f16(acc[0][2 * j],     a[0], bb);
                mma_f16(acc[1][2 * j],     a[1], bb);
                mma_f16(acc[0][2 * j + 1], a[0], bb + 2);
                mma_f16(acc[1][2 * j + 1], a[1], bb + 2);
            }
        }
    }

    // Epilogue
    #pragma unroll
    for (int nc = 0; nc < 8; nc++) {
        int col = bn + warp_n * 64 + nc * 8 + 2 * tig;
        float bv0 = bias[col], bv1 = bias[col + 1];
        #pragma unroll
        for (int mc = 0; mc < 2; mc++) {
            int row = bm + warp_m * 32 + mc * 16 + g;
            float v00 = acc[mc][nc][0] + bv0, v01 = acc[mc][nc][1] + bv1;
            float v10 = acc[mc][nc][2] + bv0, v11 = acc[mc][nc][3] + bv1;
            if (half_out) {
                __half* Ch = (__half*)Cout;
                *(__half2*)&Ch[(size_t)row * N + col]       = __floats2half2_rn(v00, v01);
                *(__half2*)&Ch[(size_t)(row + 8) * N + col] = __floats2half2_rn(v10, v11);
            } else {
                float* Cf = (float*)Cout;
                *(float2*)&Cf[(size_t)row * N + col]       = make_float2(v00, v01);
                *(float2*)&Cf[(size_t)(row + 8) * N + col] = make_float2(v10, v11);
            }
        }
    }
}

// ---------------------------------------------------------------------------
// Flash attention (causal), fp16 m16n8k16 mma, ldmatrix fragment loads,
// exp2-domain softmax. One CTA per (q-block 64, head). 128 threads = 4 warps.
// K: cp.async double-buffered [kpos][hd]. V: LDG.128 x2 + packed half2 STS
// into [hd][kpos]. P: half2 pairs. Q: regs. Word-pitch PW=36 (conflict-free).
// ---------------------------------------------------------------------------
#define PW 36
#define ROWB 144   // bytes per tile row (36 words)
#define SCALE2 0.18033688011112042f   // 0.125 * log2(e)

__global__ __launch_bounds__(128) void attn_h_kernel() {
    extern __shared__ unsigned sm[];
    unsigned* Ps = sm;                 // [64 rows][36 words] (kpos pairs)
    unsigned* Ks = Ps + 64 * PW;       // [2][64 kpos][36 words] (hd halves)
    unsigned* Vs = Ks + 2 * 64 * PW;   // [2][64 hd][36 words] (kpos pairs)

    int qb = gridDim.x - 1 - blockIdx.x;  // longest CTAs first
    int h  = blockIdx.y;
    int tid = threadIdx.x;
    int wid = tid >> 5, lane = tid & 31;
    int g = lane >> 2, tig = lane & 3;
    int row0 = wid * 16;

    const int k_off = DMODEL + h * HDIM;
    const int v_off = 2 * DMODEL + h * HDIM;

    // smem byte bases
    unsigned smb = (unsigned)__cvta_generic_to_shared(sm);
    unsigned ps_b = smb;
    unsigned ks_b = smb + 64 * ROWB;
    unsigned vs_b = ks_b + 2 * 64 * ROWB;

    // ldmatrix lane patterns
    int lm = lane >> 3, lrw = lane & 7;
    // A-type (Ps): row off (lm&1)*8, k off (lm>>1)*8
    unsigned apat = (unsigned)((row0 + (lm & 1) * 8 + lrw) * ROWB + (lm >> 1) * 16);
    // B-type (K, V): n off (lm>>1)*8, k off (lm&1)*8; per nc-pair j
    unsigned bpat[4];
    #pragma unroll
    for (int j = 0; j < 4; j++)
        bpat[j] = (unsigned)((j * 16 + (lm >> 1) * 8 + lrw) * ROWB + (lm & 1) * 16);

    // K loader (cp.async): 64 rows x 64 halves (128B/row), pitch 144B
    auto cp_k = [&](int jb, int buf) {
        char* Kd = (char*)(Ks + buf * 64 * PW);
        #pragma unroll
        for (int i = 0; i < 4; i++) {
            int linear = tid + i * 128;
            int r  = linear >> 3;
            int c8 = (linear & 7) * 8;     // half offset
            cp16(Kd + r * ROWB + c8 * 2,
                 &g_qkv_h[(size_t)(jb * 64 + r) * QKV_N + k_off + c8]);
        }
    };

    // V loader: warp wid covers hd [wid*16, +16); lane owns kpos pair (2l, 2l+1)
    int vc0 = wid * 16, vp = lane;
    uint4 vr[4];
    auto v_ldg = [&](int jb) {
        const __half* p0 = &g_qkv_h[(size_t)(jb * 64 + 2 * vp) * QKV_N + v_off + vc0];
        vr[0] = *(const uint4*)p0;
        vr[1] = *(const uint4*)(p0 + 8);
        vr[2] = *(const uint4*)(p0 + QKV_N);
        vr[3] = *(const uint4*)(p0 + QKV_N + 8);
    };
    auto v_sts = [&](int buf) {
        unsigned* Vd = Vs + buf * 64 * PW;
        const __half* r0lo = (const __half*)&vr[0];
        const __half* r0hi = (const __half*)&vr[1];
        const __half* r1lo = (const __half*)&vr[2];
        const __half* r1hi = (const __half*)&vr[3];
        #pragma unroll
        for (int j = 0; j < 8; j++) {
            __half2 w0 = __halves2half2(r0lo[j], r1lo[j]);
            Vd[(vc0 + j) * PW + vp] = *(unsigned*)&w0;
            __half2 w1 = __halves2half2(r0hi[j], r1hi[j]);
            Vd[(vc0 + 8 + j) * PW + vp] = *(unsigned*)&w1;
        }
    };

    cp_k(0, 0);
    CP_COMMIT();
    v_ldg(0);

    // Q fragments in registers
    unsigned qf[4][4];
    {
        const __half* Qb = g_qkv_h + (size_t)(qb * 64) * QKV_N + h * HDIM;
        #pragma unroll
        for (int kc = 0; kc < 4; kc++) {
            qf[kc][0] = *(const unsigned*)&Qb[(size_t)(row0 + g) * QKV_N + kc * 16 + 2 * tig];
            qf[kc][1] = *(const unsigned*)&Qb[(size_t)(row0 + g + 8) * QKV_N + kc * 16 + 2 * tig];
            qf[kc][2] = *(const unsigned*)&Qb[(size_t)(row0 + g) * QKV_N + kc * 16 + 2 * tig + 8];
            qf[kc][3] = *(const unsigned*)&Qb[(size_t)(row0 + g + 8) * QKV_N + kc * 16 + 2 * tig + 8];
        }
    }
    v_sts(0);

    float o[8][4];
    #pragma unroll
    for (int nc = 0; nc < 8; nc++)
        #pragma unroll
        for (int i = 0; i < 4; i++) o[nc][i] = 0.0f;
    float m0 = -1e30f, m1 = -1e30f, l0 = 0.0f, l1 = 0.0f;

    for (int jb = 0; jb <= qb; jb++) {
        int buf = jb & 1;
        CP_WAIT0();
        __syncthreads();

        if (jb < qb) {
            cp_k(jb + 1, buf ^ 1);
            CP_COMMIT();
            v_ldg(jb + 1);
        }

        unsigned kc_b = ks_b + buf * 64 * ROWB;
        unsigned vc_b = vs_b + buf * 64 * ROWB;

        // ---- S = Q @ K^T (ldmatrix B-frags) ----
        float s[8][4];
        #pragma unroll
        for (int nc = 0; nc < 8; nc++)
            #pragma unroll
            for (int i = 0; i < 4; i++) s[nc][i] = 0.0f;

        #pragma unroll
        for (int kc = 0; kc < 4; kc++) {
            #pragma unroll
            for (int j = 0; j < 4; j++) {
                unsigned bb[4];
                ldsm_x4(bb, kc_b + bpat[j] + kc * 32);
                mma_f16(s[2 * j],     qf[kc], bb);
                mma_f16(s[2 * j + 1], qf[kc], bb + 2);
            }
        }

        #pragma unroll
        for (int nc = 0; nc < 8; nc++)
            #pragma unroll
            for (int i = 0; i < 4; i++) s[nc][i] *= SCALE2;   // log2-domain scores

        if (jb == qb) {
            int r_lo = row0 + g, r_hi = row0 + g + 8;
            #pragma unroll
            for (int nc = 0; nc < 8; nc++) {
                int c0 = nc * 8 + 2 * tig, c1 = c0 + 1;
                if (c0 > r_lo) s[nc][0] = -1e30f;
                if (c1 > r_lo) s[nc][1] = -1e30f;
                if (c0 > r_hi) s[nc][2] = -1e30f;
                if (c1 > r_hi) s[nc][3] = -1e30f;
            }
        }

        if (jb < qb) v_sts(buf ^ 1);

        float mx0 = -1e30f, mx1 = -1e30f;
        #pragma unroll
        for (int nc = 0; nc < 8; nc++) {
            mx0 = fmaxf(mx0, fmaxf(s[nc][0], s[nc][1]));
            mx1 = fmaxf(mx1, fmaxf(s[nc][2], s[nc][3]));
        }
        mx0 = fmaxf(mx0, __shfl_xor_sync(0xffffffffu, mx0, 1));
        mx0 = fmaxf(mx0, __shfl_xor_sync(0xffffffffu, mx0, 2));
        mx1 = fmaxf(mx1, __shfl_xor_sync(0xffffffffu, mx1, 1));
        mx1 = fmaxf(mx1, __shfl_xor_sync(0xffffffffu, mx1, 2));

        float mn0 = fmaxf(m0, mx0), mn1 = fmaxf(m1, mx1);
        float al0 = ex2(m0 - mn0), al1 = ex2(m1 - mn1);

        float rs0 = 0.0f, rs1 = 0.0f;
        #pragma unroll
        for (int nc = 0; nc < 8; nc++) {
            float p0 = ex2(s[nc][0] - mn0);
            float p1 = ex2(s[nc][1] - mn0);
            float p2 = ex2(s[nc][2] - mn1);
            float p3 = ex2(s[nc][3] - mn1);
            rs0 += p0 + p1;
            rs1 += p2 + p3;
            __half2 lo = __floats2half2_rn(p0, p1);
            __half2 hi = __floats2half2_rn(p2, p3);
            Ps[(row0 + g) * PW + nc * 4 + tig]     = *(unsigned*)&lo;
            Ps[(row0 + g + 8) * PW + nc * 4 + tig] = *(unsigned*)&hi;
        }
        rs0 += __shfl_xor_sync(0xffffffffu, rs0, 1);
        rs0 += __shfl_xor_sync(0xffffffffu, rs0, 2);
        rs1 += __shfl_xor_sync(0xffffffffu, rs1, 1);
        rs1 += __shfl_xor_sync(0xffffffffu, rs1, 2);

        l0 = l0 * al0 + rs0;
        l1 = l1 * al1 + rs1;
        m0 = mn0;
        m1 = mn1;
        #pragma unroll
        for (int nc = 0; nc < 8; nc++) {
            o[nc][0] *= al0; o[nc][1] *= al0;
            o[nc][2] *= al1; o[nc][3] *= al1;
        }
        __syncwarp();   // Ps rows are warp-private

        // ---- O += P @ V (ldmatrix A- and B-frags) ----
        #pragma unroll
        for (int kc = 0; kc < 4; kc++) {
            unsigned a[4];
            ldsm_x4(a, ps_b + apat + kc * 32);
            #pragma unroll
            for (int j = 0; j < 4; j++) {
                unsigned bb[4];
                ldsm_x4(bb, vc_b + bpat[j] + kc * 32);
                mma_f16(o[2 * j],     a, bb);
                mma_f16(o[2 * j + 1], a, bb + 2);
            }
        }
    }

    // Normalize, write ctx (fp16)
    float inv0 = 1.0f / l0, inv1 = 1.0f / l1;
    #pragma unroll
    for (int nc = 0; nc < 8; nc++) {
        int col = h * HDIM + nc * 8 + 2 * tig;
        int r_lo = qb * 64 + row0 + g;
        __half2 lo = __floats2half2_rn(o[nc][0] * inv0, o[nc][1] * inv0);
        __half2 hi = __floats2half2_rn(o[nc][2] * inv1, o[nc][3] * inv1);
        *(__half2*)&g_ctx_h[(size_t)r_lo * DMODEL + col]       = lo;
        *(__half2*)&g_ctx_h[(size_t)(r_lo + 8) * DMODEL + col] = hi;
    }
}

// ---------------------------------------------------------------------------
extern "C" void kernel_launch(void* const* d_in, const int* in_sizes, int n_in,
                              void* d_out, int out_size) {
    (void)in_sizes; (void)n_in; (void)out_size;
    const float* x     = (const float*)d_in[0];
    const float* w_qkv = (const float*)d_in[1];
    const float* b_qkv = (const float*)d_in[2];
    const float* w_out = (const float*)d_in[3];
    const float* b_out = (const float*)d_in[4];
    float* out = (float*)d_out;

    __half *qkv_ptr, *ctx_ptr, *xh_ptr, *wqkvT_ptr, *woutT_ptr;
    cudaGetSymbolAddress((void**)&qkv_ptr,   g_qkv_h);
    cudaGetSymbolAddress((void**)&ctx_ptr,   g_ctx_h);
    cudaGetSymbolAddress((void**)&xh_ptr,    g_x_h);
    cudaGetSymbolAddress((void**)&wqkvT_ptr, g_wqkvT_h);
    cudaGetSymbolAddress((void**)&woutT_ptr, g_woutT_h);

    const int ATTN_SMEM = 5 * 64 * PW * (int)sizeof(unsigned);   // 46080
    static bool attr_set = false;
    if (!attr_set) {
        cudaFuncSetAttribute(attn_h_kernel,
                             cudaFuncAttributeMaxDynamicSharedMemorySize, ATTN_SMEM);
        attr_set = true;
    }

    // 0) Convert inputs: x -> fp16; weights -> transposed fp16 [N][K]
    f2h_kernel<<<(SEQ * DMODEL / 4 + 255) / 256, 256>>>(x, xh_ptr, SEQ * DMODEL / 4);
    transpose_h_kernel<<<dim3(QKV_N / 32, DMODEL / 32), dim3(32, 8)>>>(
        w_qkv, wqkvT_ptr, DMODEL, QKV_N);
    transpose_h_kernel<<<dim3(DMODEL / 32, DMODEL / 32), dim3(32, 8)>>>(
        w_out, woutT_ptr, DMODEL, DMODEL);

    // 1) QKV projection (fp16 out)
    gemm_h_kernel<<<dim3(QKV_N / 128, SEQ / 128), 256>>>(
        xh_ptr, wqkvT_ptr, b_qkv, qkv_ptr, SEQ, QKV_N, DMODEL, 1);

    // 2) Causal attention
    attn_h_kernel<<<dim3(SEQ / 64, NHEADS), 128, ATTN_SMEM>>>();

    // 3) Output projection (fp32 out)
    gemm_h_kernel<<<dim3(DMODEL / 128, SEQ / 128), 256>>>(
        ctx_ptr, woutT_ptr, b_out, out, SEQ, DMODEL, DMODEL, 0);
}